// round 9
// baseline (speedup 1.0000x reference)
#include <cuda_runtime.h>
#include <math.h>

typedef unsigned long long u64t;

#define EM1 4
#define NN 64
#define FF 32
#define U1C 128
#define U2C 64
#define UAC 128
#define NT 1024
#define BATCH 2048

#define ADJ_PITCH 65
#define NODE_PITCH 36
#define AN_PITCH 36
#define H1_PITCH 132
#define P2_PITCH 68
#define GP_PITCH 132
#define H2_PITCH 68

#define OFF_ADJ 0
#define OFF_NODE (OFF_ADJ + EM1*NN*ADJ_PITCH)    // 16640
#define OFF_RS   (OFF_NODE + NN*NODE_PITCH)      // 18944
#define OFF_H1   (OFF_RS + EM1*NN)               // 19200
#define OFF_U    (OFF_H1 + NN*H1_PITCH)          // 27648 (an 9216 / pre2 17408 / gates 16896 union)
#define OFF_H2   (OFF_U + EM1*NN*P2_PITCH)       // 45056
#define OFF_RED  (OFF_H2 + NN*H2_PITCH)          // 49408
#define SMEM_FLOATS (OFF_RED + 8*UAC)            // 50432
#define SMEM_BYTES (SMEM_FLOATS * 4)             // 201728 B

// ---- packed fp32x2 (Blackwell f32x2 pipe: 2x FFMA rate) ----
__device__ __forceinline__ u64t ffma2(u64t acc, u64t w, u64t a2) {
    u64t r;
    asm("fma.rn.f32x2 %0, %1, %2, %3;" : "=l"(r) : "l"(w), "l"(a2), "l"(acc));
    return r;
}
__device__ __forceinline__ u64t splat2(float a) {
    u64t r; asm("mov.b64 %0, {%1, %1};" : "=l"(r) : "f"(a)); return r;
}
__device__ __forceinline__ float2 unpack2(u64t v) {
    float2 f; asm("mov.b64 {%0, %1}, %2;" : "=f"(f.x), "=f"(f.y) : "l"(v)); return f;
}
__device__ __forceinline__ float sigmoidf_(float x) { return 1.0f / (1.0f + expf(-x)); }

__global__ void __launch_bounds__(NT, 1)
encoder_kernel(const float* __restrict__ adjacency,
               const float* __restrict__ node,
               const float* __restrict__ W1, const float* __restrict__ b1,
               const float* __restrict__ V1, const float* __restrict__ c1,
               const float* __restrict__ W2, const float* __restrict__ b2,
               const float* __restrict__ V2, const float* __restrict__ c2,
               const float* __restrict__ Wi, const float* __restrict__ bi,
               const float* __restrict__ Wj, const float* __restrict__ bj,
               float* __restrict__ out)
{
    extern __shared__ float smem[];
    const int b = blockIdx.x;
    const int tid = threadIdx.x;
    const int wid = tid >> 5;
    const int lane = tid & 31;

    // ---------------- Phase A: stage adjacency (transposed, drop edge 0) + node ----------
    {
        const float* adjB = adjacency + (size_t)b * (NN * NN * 5);
        for (int idx = tid; idx < NN * NN * 5; idx += NT) {
            float v = adjB[idx];
            int e = idx % 5;
            int r = idx / 5;           // r = m*64 + n
            if (e > 0)
                smem[OFF_ADJ + ((e - 1) * NN + (r >> 6)) * ADJ_PITCH + (r & 63)] = v;
        }
        const float* nodeB = node + (size_t)b * (NN * FF);
        for (int idx = tid; idx < NN * FF; idx += NT)
            smem[OFF_NODE + (idx >> 5) * NODE_PITCH + (idx & 31)] = nodeB[idx];
    }
    __syncthreads();

    // ---------------- Phase B: an[e][m][f] = adj_e @ node ; rowsum[e][m] -----------------
    // 32 warps = 4 e x 8 f-slices of 4; lane = m (and m+32). per n: 2 LDS.32 + 1 uniform LDS.128 -> 4 FFMA2
    {
        const int e = wid >> 3;
        const int fs = wid & 7;
        const int f0 = fs * 4;
        u64t acc[2][2];
        acc[0][0] = acc[0][1] = acc[1][0] = acc[1][1] = 0ull;
        float rs0 = 0.0f, rs1 = 0.0f;
        const float* a0p = &smem[OFF_ADJ + (e * NN + lane) * ADJ_PITCH];
        const float* a1p = a0p + 32 * ADJ_PITCH;
        const float* nodep = &smem[OFF_NODE + f0];
        #pragma unroll 4
        for (int n = 0; n < NN; n++) {
            float a0 = a0p[n], a1 = a1p[n];
            rs0 += a0; rs1 += a1;
            u64t s0 = splat2(a0), s1 = splat2(a1);
            ulonglong2 v = *(const ulonglong2*)(nodep + n * NODE_PITCH);
            acc[0][0] = ffma2(acc[0][0], v.x, s0); acc[0][1] = ffma2(acc[0][1], v.y, s0);
            acc[1][0] = ffma2(acc[1][0], v.x, s1); acc[1][1] = ffma2(acc[1][1], v.y, s1);
        }
        #pragma unroll
        for (int mh = 0; mh < 2; mh++) {
            float* an = &smem[OFF_U + (e * NN + lane + mh * 32) * AN_PITCH + f0];
            *(ulonglong2*)an = make_ulonglong2(acc[mh][0], acc[mh][1]);
        }
        if (fs == 0) {
            smem[OFF_RS + e * NN + lane]      = rs0;
            smem[OFF_RS + e * NN + lane + 32] = rs1;
        }
    }
    __syncthreads();

    // ---------------- Phase C: h1[m][u]=tanh(sum_e an_e@W1_e + rs_e*b1_e + node@V1 + c1) --
    // 32 warps = u-slices of 4; lane = m (and m+32).
    {
        const int ml = lane;
        const int u0 = wid * 4;
        u64t acc[2][2];
        {
            ulonglong2 cA = *(const ulonglong2*)(c1 + u0);
            acc[0][0] = cA.x; acc[0][1] = cA.y;
            acc[1][0] = cA.x; acc[1][1] = cA.y;
        }
        #pragma unroll 1
        for (int e = 0; e < EM1; e++) {
            const float* anb = &smem[OFF_U + (e * NN + ml) * AN_PITCH];
            const float* w1b = W1 + e * FF * U1C + u0;
            #pragma unroll 2
            for (int f4 = 0; f4 < FF; f4 += 4) {
                float a0[4], a1[4];
                *(float4*)a0 = *(const float4*)(anb + f4);
                *(float4*)a1 = *(const float4*)(anb + 32 * AN_PITCH + f4);
                #pragma unroll
                for (int j = 0; j < 4; j++) {
                    ulonglong2 wA = *(const ulonglong2*)(w1b + (f4 + j) * U1C);
                    u64t s0 = splat2(a0[j]), s1 = splat2(a1[j]);
                    acc[0][0] = ffma2(acc[0][0], wA.x, s0); acc[0][1] = ffma2(acc[0][1], wA.y, s0);
                    acc[1][0] = ffma2(acc[1][0], wA.x, s1); acc[1][1] = ffma2(acc[1][1], wA.y, s1);
                }
            }
        }
        #pragma unroll
        for (int e = 0; e < EM1; e++) {
            ulonglong2 wA = *(const ulonglong2*)(b1 + e * U1C + u0);
            u64t s0 = splat2(smem[OFF_RS + e * NN + ml]);
            u64t s1 = splat2(smem[OFF_RS + e * NN + ml + 32]);
            acc[0][0] = ffma2(acc[0][0], wA.x, s0); acc[0][1] = ffma2(acc[0][1], wA.y, s0);
            acc[1][0] = ffma2(acc[1][0], wA.x, s1); acc[1][1] = ffma2(acc[1][1], wA.y, s1);
        }
        {
            const float* nb0 = &smem[OFF_NODE + ml * NODE_PITCH];
            const float* nb1 = &smem[OFF_NODE + (ml + 32) * NODE_PITCH];
            #pragma unroll 2
            for (int f4 = 0; f4 < FF; f4 += 4) {
                float a0[4], a1[4];
                *(float4*)a0 = *(const float4*)(nb0 + f4);
                *(float4*)a1 = *(const float4*)(nb1 + f4);
                #pragma unroll
                for (int j = 0; j < 4; j++) {
                    ulonglong2 wA = *(const ulonglong2*)(V1 + (f4 + j) * U1C + u0);
                    u64t s0 = splat2(a0[j]), s1 = splat2(a1[j]);
                    acc[0][0] = ffma2(acc[0][0], wA.x, s0); acc[0][1] = ffma2(acc[0][1], wA.y, s0);
                    acc[1][0] = ffma2(acc[1][0], wA.x, s1); acc[1][1] = ffma2(acc[1][1], wA.y, s1);
                }
            }
        }
        #pragma unroll
        for (int im = 0; im < 2; im++) {
            int m = ml + im * 32;
            float* h = &smem[OFF_H1 + m * H1_PITCH + u0];
            float2 x0 = unpack2(acc[im][0]), x1 = unpack2(acc[im][1]);
            *(float4*)h = make_float4(tanhf(x0.x), tanhf(x0.y), tanhf(x1.x), tanhf(x1.y));
        }
    }
    __syncthreads();

    // ---------------- Phase D: pre2[e][n][u] = [h1,node][n] @ W2[e] + b2[e] ---------------
    // 256 threads per e: lane n (stride 16, 4 n's) x 16 u-slices of 4.
    {
        const int e = tid >> 8;
        const int r = tid & 255;
        const int nl = r & 15;
        const int ug = r >> 4;            // 0..15
        const int u0 = ug * 4;
        u64t acc[4][2];
        {
            ulonglong2 bA = *(const ulonglong2*)(b2 + e * U2C + u0);
            #pragma unroll
            for (int im = 0; im < 4; im++) { acc[im][0] = bA.x; acc[im][1] = bA.y; }
        }
        const float* w2b = W2 + e * (U1C + FF) * U2C + u0;
        const float* h1b = &smem[OFF_H1 + nl * H1_PITCH];
        #pragma unroll 1
        for (int k4 = 0; k4 < U1C; k4 += 4) {
            float a[4][4];
            #pragma unroll
            for (int im = 0; im < 4; im++)
                *(float4*)a[im] = *(const float4*)(h1b + im * 16 * H1_PITCH + k4);
            #pragma unroll
            for (int j = 0; j < 4; j++) {
                ulonglong2 wA = *(const ulonglong2*)(w2b + (k4 + j) * U2C);
                #pragma unroll
                for (int im = 0; im < 4; im++) {
                    u64t s = splat2(a[im][j]);
                    acc[im][0] = ffma2(acc[im][0], wA.x, s);
                    acc[im][1] = ffma2(acc[im][1], wA.y, s);
                }
            }
        }
        const float* nb = &smem[OFF_NODE + nl * NODE_PITCH];
        #pragma unroll 1
        for (int k4 = 0; k4 < FF; k4 += 4) {
            float a[4][4];
            #pragma unroll
            for (int im = 0; im < 4; im++)
                *(float4*)a[im] = *(const float4*)(nb + im * 16 * NODE_PITCH + k4);
            #pragma unroll
            for (int j = 0; j < 4; j++) {
                ulonglong2 wA = *(const ulonglong2*)(w2b + (U1C + k4 + j) * U2C);
                #pragma unroll
                for (int im = 0; im < 4; im++) {
                    u64t s = splat2(a[im][j]);
                    acc[im][0] = ffma2(acc[im][0], wA.x, s);
                    acc[im][1] = ffma2(acc[im][1], wA.y, s);
                }
            }
        }
        #pragma unroll
        for (int im = 0; im < 4; im++) {
            float* dst = &smem[OFF_U + (e * NN + nl + 16 * im) * P2_PITCH + u0];
            *(ulonglong2*)dst = make_ulonglong2(acc[im][0], acc[im][1]);
        }
    }
    __syncthreads();

    // ---------------- Phase E: h2[m][u] = tanh(sum_e adj_e @ pre2_e + node@V2 + c2) -------
    // 32 warps = 16 u-slices of 4 x 2 m-halves; lane = m. per n: 1 LDS.32 + 1 uniform LDS.128 -> 2 FFMA2
    {
        const int us = wid & 15;
        const int mh = wid >> 4;
        const int u0 = us * 4;
        const int m = mh * 32 + lane;
        u64t acc[2];
        {
            ulonglong2 cA = *(const ulonglong2*)(c2 + u0);
            acc[0] = cA.x; acc[1] = cA.y;
        }
        #pragma unroll 1
        for (int e = 0; e < EM1; e++) {
            const float* adjb = &smem[OFF_ADJ + (e * NN + m) * ADJ_PITCH];
            const float* p2b = &smem[OFF_U + e * NN * P2_PITCH + u0];
            #pragma unroll 4
            for (int n = 0; n < NN; n++) {
                ulonglong2 w = *(const ulonglong2*)(p2b + n * P2_PITCH);
                u64t s = splat2(adjb[n]);
                acc[0] = ffma2(acc[0], w.x, s); acc[1] = ffma2(acc[1], w.y, s);
            }
        }
        {
            const float* nb = &smem[OFF_NODE + m * NODE_PITCH];
            #pragma unroll 2
            for (int f4 = 0; f4 < FF; f4 += 4) {
                float a[4];
                *(float4*)a = *(const float4*)(nb + f4);
                #pragma unroll
                for (int j = 0; j < 4; j++) {
                    ulonglong2 w = *(const ulonglong2*)(V2 + (f4 + j) * U2C + u0);
                    u64t s = splat2(a[j]);
                    acc[0] = ffma2(acc[0], w.x, s); acc[1] = ffma2(acc[1], w.y, s);
                }
            }
        }
        {
            float* h = &smem[OFF_H2 + m * H2_PITCH + u0];
            float2 x0 = unpack2(acc[0]), x1 = unpack2(acc[1]);
            *(float4*)h = make_float4(tanhf(x0.x), tanhf(x0.y), tanhf(x1.x), tanhf(x1.y));
        }
    }
    __syncthreads();

    // ---------------- Phase F: gate pre-activations ----------------------------------------
    // 512 threads per matrix: lane n (stride 16, 4 n's) x 32 u-slices of 4.
    {
        const int mat = tid >> 9;         // 0 -> Wi/bi, 1 -> Wj/bj
        const int r = tid & 511;
        const int nl = r & 15;
        const int ug = r >> 4;            // 0..31
        const int u0 = ug * 4;
        const float* W = mat ? Wj : Wi;
        const float* bv = mat ? bj : bi;
        u64t acc[4][2];
        {
            ulonglong2 bA = *(const ulonglong2*)(bv + u0);
            #pragma unroll
            for (int im = 0; im < 4; im++) { acc[im][0] = bA.x; acc[im][1] = bA.y; }
        }
        const float* h2b = &smem[OFF_H2 + nl * H2_PITCH];
        #pragma unroll 1
        for (int k4 = 0; k4 < U2C; k4 += 4) {
            float a[4][4];
            #pragma unroll
            for (int im = 0; im < 4; im++)
                *(float4*)a[im] = *(const float4*)(h2b + im * 16 * H2_PITCH + k4);
            #pragma unroll
            for (int j = 0; j < 4; j++) {
                ulonglong2 wA = *(const ulonglong2*)(W + (k4 + j) * UAC + u0);
                #pragma unroll
                for (int im = 0; im < 4; im++) {
                    u64t s = splat2(a[im][j]);
                    acc[im][0] = ffma2(acc[im][0], wA.x, s);
                    acc[im][1] = ffma2(acc[im][1], wA.y, s);
                }
            }
        }
        const float* nb = &smem[OFF_NODE + nl * NODE_PITCH];
        #pragma unroll 1
        for (int k4 = 0; k4 < FF; k4 += 4) {
            float a[4][4];
            #pragma unroll
            for (int im = 0; im < 4; im++)
                *(float4*)a[im] = *(const float4*)(nb + im * 16 * NODE_PITCH + k4);
            #pragma unroll
            for (int j = 0; j < 4; j++) {
                ulonglong2 wA = *(const ulonglong2*)(W + (U2C + k4 + j) * UAC + u0);
                #pragma unroll
                for (int im = 0; im < 4; im++) {
                    u64t s = splat2(a[im][j]);
                    acc[im][0] = ffma2(acc[im][0], wA.x, s);
                    acc[im][1] = ffma2(acc[im][1], wA.y, s);
                }
            }
        }
        #pragma unroll
        for (int im = 0; im < 4; im++) {
            float* dst = &smem[OFF_U + (mat * NN + nl + 16 * im) * GP_PITCH + u0];
            *(ulonglong2*)dst = make_ulonglong2(acc[im][0], acc[im][1]);
        }
    }
    __syncthreads();

    // ---------------- Phase G: out[b][u] = tanh(sum_n sigmoid(pi)*tanh(pj)) ----------------
    {
        const int q = tid >> 7;           // 0..7
        const int u = tid & 127;
        float s = 0.0f;
        #pragma unroll
        for (int i = 0; i < 8; i++) {
            int n = q * 8 + i;
            float pi = smem[OFF_U + n * GP_PITCH + u];
            float pj = smem[OFF_U + (NN + n) * GP_PITCH + u];
            s += sigmoidf_(pi) * tanhf(pj);
        }
        smem[OFF_RED + q * UAC + u] = s;
    }
    __syncthreads();
    if (tid < UAC) {
        float s = 0.0f;
        #pragma unroll
        for (int q = 0; q < 8; q++)
            s += smem[OFF_RED + q * UAC + tid];
        out[(size_t)b * UAC + tid] = tanhf(s);
    }
}

extern "C" void kernel_launch(void* const* d_in, const int* in_sizes, int n_in,
                              void* d_out, int out_size) {
    (void)in_sizes; (void)n_in; (void)out_size;
    const float* adjacency = (const float*)d_in[0];
    // d_in[1] = hidden (rank-2, unused by the encoder math)
    const float* node = (const float*)d_in[2];
    const float* W1 = (const float*)d_in[3];
    const float* b1 = (const float*)d_in[4];
    const float* V1 = (const float*)d_in[5];
    const float* c1 = (const float*)d_in[6];
    const float* W2 = (const float*)d_in[7];
    const float* b2 = (const float*)d_in[8];
    const float* V2 = (const float*)d_in[9];
    const float* c2 = (const float*)d_in[10];
    const float* Wi = (const float*)d_in[11];
    const float* bi = (const float*)d_in[12];
    const float* Wj = (const float*)d_in[13];
    const float* bj = (const float*)d_in[14];

    cudaFuncSetAttribute(encoder_kernel,
                         cudaFuncAttributeMaxDynamicSharedMemorySize, SMEM_BYTES);
    encoder_kernel<<<BATCH, NT, SMEM_BYTES>>>(adjacency, node,
                                              W1, b1, V1, c1,
                                              W2, b2, V2, c2,
                                              Wi, bi, Wj, bj,
                                              (float*)d_out);
}

// round 11
// speedup vs baseline: 1.3889x; 1.3889x over previous
#include <cuda_runtime.h>
#include <cuda_bf16.h>
#include <math.h>
#include <cstdint>

typedef unsigned long long u64t;
typedef unsigned int u32t;

#define EM1 4
#define NN 64
#define FF 32
#define U1C 128
#define U2C 64
#define UAC 128
#define NT 512
#define BATCH 2048

#define ADJ_PITCH 65
#define NODE_PITCH 36
#define AN_PITCH 36
#define P2_PITCH 68
#define PI_PITCH 132

// ---- smem regions (float indices) ----
#define R_ADJ 0            // adjacency [4][64][65] = 16640 (alive through E)
#define R_NODE 16640       // node [64][36] = 2304
#define R_RS 18944         // rowsums 256
#define R_AN 19200         // an [4][64][36] = 9216 (B->C); then F act tiles
#define R_FAH 19200        // F act hi bf16 [64 rows][pitch 224B] = 3584 fl
#define R_FAL 22784        // F act lo
#define R_DAH 28416        // D act hi bf16 [64][pitch 336B] = 5376 fl
#define R_DAL 33792        // D act lo
#define R_P2  39168        // pre2 fp32 [256][68] = 17408 (D-epi -> E)
#define R_WCH 39168        // ALIAS: weight chunk [2][256 rows][48B] = 6144 fl (only mid-D / mid-F)
#define R_PI  39168        // ALIAS: pi [64][132] (F-epi -> G)
#define R_PJ  47616        // pj [64][132]
#define R_RED 56576        // 512
#define SMEM_FLOATS 57088
#define SMEM_BYTES (SMEM_FLOATS*4)   // 228352 B

// packed bf16 weights, [split][row=u][k] row-major
__device__ __align__(16) __nv_bfloat16 g_W2pack[2][256][160];  // W2: row = e*64+u, k=0..159
__device__ __align__(16) __nv_bfloat16 g_WGpack[2][256][96];   // gates: row = mat*128+u, k=0..95

// ---- fp32x2 helpers ----
__device__ __forceinline__ u64t ffma2(u64t a, u64t w, u64t s) {
    u64t r; asm("fma.rn.f32x2 %0, %1, %2, %3;" : "=l"(r) : "l"(w), "l"(s), "l"(a)); return r;
}
__device__ __forceinline__ u64t splat2(float a) {
    u64t r; asm("mov.b64 %0, {%1, %1};" : "=l"(r) : "f"(a)); return r;
}
__device__ __forceinline__ float2 unpack2(u64t v) {
    float2 f; asm("mov.b64 {%0, %1}, %2;" : "=f"(f.x), "=f"(f.y) : "l"(v)); return f;
}
__device__ __forceinline__ float sigmoidf_(float x) { return 1.0f / (1.0f + expf(-x)); }

// ---- bf16 helpers ----
__device__ __forceinline__ u32t bfpair(float a, float b) {
    u32t lo = (u32t)__bfloat16_as_ushort(__float2bfloat16_rn(a));
    u32t hi = (u32t)__bfloat16_as_ushort(__float2bfloat16_rn(b));
    return lo | (hi << 16);
}
__device__ __forceinline__ float bflo(float x) { return x - __bfloat162float(__float2bfloat16_rn(x)); }

__device__ __forceinline__ u32t smem_u32(const void* p) {
    u32t a; asm("{ .reg .u64 t; cvta.to.shared.u64 t, %1; cvt.u32.u64 %0, t; }" : "=r"(a) : "l"(p));
    return a;
}

#define LDSM_X4(r0, r1, r2, r3, addr) \
    asm volatile("ldmatrix.sync.aligned.m8n8.x4.shared.b16 {%0,%1,%2,%3}, [%4];" \
                 : "=r"(r0), "=r"(r1), "=r"(r2), "=r"(r3) : "r"(addr))

#define MMA_BF16(c, a0, a1, a2, a3, b0, b1) \
    asm volatile("mma.sync.aligned.m16n8k16.row.col.f32.bf16.bf16.f32 " \
                 "{%0,%1,%2,%3}, {%4,%5,%6,%7}, {%8,%9}, {%0,%1,%2,%3};" \
                 : "+f"((c)[0]), "+f"((c)[1]), "+f"((c)[2]), "+f"((c)[3]) \
                 : "r"(a0), "r"(a1), "r"(a2), "r"(a3), "r"(b0), "r"(b1))

// ---- weight preconversion: [u][k] bf16 hi/lo split ----
__global__ void preconv_kernel(const float* __restrict__ W2,
                               const float* __restrict__ Wi,
                               const float* __restrict__ Wj) {
    int i = blockIdx.x * 256 + threadIdx.x;
    if (i < 256 * 160) {
        int row = i / 160, k = i % 160;
        int e = row >> 6, u = row & 63;
        float w = W2[(e * 160 + k) * 64 + u];
        __nv_bfloat16 h = __float2bfloat16_rn(w);
        g_W2pack[0][row][k] = h;
        g_W2pack[1][row][k] = __float2bfloat16_rn(w - __bfloat162float(h));
    } else if (i < 256 * 160 + 256 * 96) {
        int j = i - 256 * 160;
        int row = j / 96, k = j % 96;
        int mat = row >> 7, u = row & 127;
        float w = (mat ? Wj : Wi)[k * 128 + u];
        __nv_bfloat16 h = __float2bfloat16_rn(w);
        g_WGpack[0][row][k] = h;
        g_WGpack[1][row][k] = __float2bfloat16_rn(w - __bfloat162float(h));
    }
}

__global__ void __launch_bounds__(NT, 1)
encoder_kernel(const float* __restrict__ adjacency,
               const float* __restrict__ node,
               const float* __restrict__ W1, const float* __restrict__ b1,
               const float* __restrict__ V1, const float* __restrict__ c1,
               const float* __restrict__ b2, const float* __restrict__ V2,
               const float* __restrict__ c2,
               const float* __restrict__ bi, const float* __restrict__ bj,
               float* __restrict__ out)
{
    extern __shared__ float smem[];
    char* smc = (char*)smem;
    const int b = blockIdx.x;
    const int tid = threadIdx.x;
    const int wid = tid >> 5;
    const int lane = tid & 31;
    const u32t smb = smem_u32(smem);

    // ---------------- Phase A: stage adjacency (transposed, drop edge 0) + node ----------
    {
        const float* adjB = adjacency + (size_t)b * (NN * NN * 5);
        for (int idx = tid; idx < NN * NN * 5; idx += NT) {
            float v = adjB[idx];
            int e = idx % 5;
            int r = idx / 5;
            if (e > 0)
                smem[R_ADJ + ((e - 1) * NN + (r >> 6)) * ADJ_PITCH + (r & 63)] = v;
        }
        const float* nodeB = node + (size_t)b * (NN * FF);
        for (int idx = tid; idx < NN * FF; idx += NT)
            smem[R_NODE + (idx >> 5) * NODE_PITCH + (idx & 31)] = nodeB[idx];
    }
    __syncthreads();

    // ---------------- Phase B: an = adj_e @ node ; rowsums ; D-act node cols (k 128..159) --
    {
        const int e = wid >> 2, fs = wid & 3, f0 = fs * 8;
        u64t acc[2][4];
        #pragma unroll
        for (int mh = 0; mh < 2; mh++)
            #pragma unroll
            for (int j = 0; j < 4; j++) acc[mh][j] = 0ull;
        float rs0 = 0.f, rs1 = 0.f;
        const float* a0p = &smem[R_ADJ + (e * NN + lane) * ADJ_PITCH];
        const float* a1p = a0p + 32 * ADJ_PITCH;
        const float* np = &smem[R_NODE + f0];
        #pragma unroll 4
        for (int n = 0; n < NN; n++) {
            float a0 = a0p[n], a1 = a1p[n];
            rs0 += a0; rs1 += a1;
            u64t s0 = splat2(a0), s1 = splat2(a1);
            ulonglong2 v0 = *(const ulonglong2*)(np + n * NODE_PITCH);
            ulonglong2 v1 = *(const ulonglong2*)(np + n * NODE_PITCH + 4);
            acc[0][0] = ffma2(acc[0][0], v0.x, s0); acc[0][1] = ffma2(acc[0][1], v0.y, s0);
            acc[0][2] = ffma2(acc[0][2], v1.x, s0); acc[0][3] = ffma2(acc[0][3], v1.y, s0);
            acc[1][0] = ffma2(acc[1][0], v0.x, s1); acc[1][1] = ffma2(acc[1][1], v0.y, s1);
            acc[1][2] = ffma2(acc[1][2], v1.x, s1); acc[1][3] = ffma2(acc[1][3], v1.y, s1);
        }
        #pragma unroll
        for (int mh = 0; mh < 2; mh++) {
            float* an = &smem[R_AN + (e * NN + lane + mh * 32) * AN_PITCH + f0];
            *(ulonglong2*)an       = make_ulonglong2(acc[mh][0], acc[mh][1]);
            *(ulonglong2*)(an + 4) = make_ulonglong2(acc[mh][2], acc[mh][3]);
        }
        if (fs == 0) {
            smem[R_RS + e * NN + lane]      = rs0;
            smem[R_RS + e * NN + lane + 32] = rs1;
        }
        // D act tile cols 128..159 = node cols 0..31
        for (int idx = tid; idx < NN * 32; idx += NT) {
            int r = idx >> 5, k = 128 + (idx & 31);
            float v = smem[R_NODE + r * NODE_PITCH + (k - 128)];
            *(unsigned short*)(smc + R_DAH * 4 + r * 336 + k * 2) =
                __bfloat16_as_ushort(__float2bfloat16_rn(v));
            *(unsigned short*)(smc + R_DAL * 4 + r * 336 + k * 2) =
                __bfloat16_as_ushort(__float2bfloat16_rn(bflo(v)));
        }
    }
    __syncthreads();

    // ---------------- Phase C: h1 = tanh(...) -> D act tiles cols 0..127 -------------------
    {
        const int ml = lane, u0 = wid * 8;
        u64t acc[2][4];
        {
            ulonglong2 cA = *(const ulonglong2*)(c1 + u0);
            ulonglong2 cB = *(const ulonglong2*)(c1 + u0 + 4);
            #pragma unroll
            for (int im = 0; im < 2; im++) {
                acc[im][0] = cA.x; acc[im][1] = cA.y;
                acc[im][2] = cB.x; acc[im][3] = cB.y;
            }
        }
        #pragma unroll 1
        for (int e = 0; e < EM1; e++) {
            const float* anb = &smem[R_AN + (e * NN + ml) * AN_PITCH];
            const float* w1b = W1 + e * FF * U1C + u0;
            #pragma unroll 2
            for (int f4 = 0; f4 < FF; f4 += 4) {
                float a0[4], a1[4];
                *(float4*)a0 = *(const float4*)(anb + f4);
                *(float4*)a1 = *(const float4*)(anb + 32 * AN_PITCH + f4);
                #pragma unroll
                for (int j = 0; j < 4; j++) {
                    const float* wr = w1b + (f4 + j) * U1C;
                    ulonglong2 wA = *(const ulonglong2*)(wr);
                    ulonglong2 wB = *(const ulonglong2*)(wr + 4);
                    u64t s0 = splat2(a0[j]), s1 = splat2(a1[j]);
                    acc[0][0] = ffma2(acc[0][0], wA.x, s0); acc[0][1] = ffma2(acc[0][1], wA.y, s0);
                    acc[0][2] = ffma2(acc[0][2], wB.x, s0); acc[0][3] = ffma2(acc[0][3], wB.y, s0);
                    acc[1][0] = ffma2(acc[1][0], wA.x, s1); acc[1][1] = ffma2(acc[1][1], wA.y, s1);
                    acc[1][2] = ffma2(acc[1][2], wB.x, s1); acc[1][3] = ffma2(acc[1][3], wB.y, s1);
                }
            }
        }
        #pragma unroll
        for (int e = 0; e < EM1; e++) {
            ulonglong2 wA = *(const ulonglong2*)(b1 + e * U1C + u0);
            ulonglong2 wB = *(const ulonglong2*)(b1 + e * U1C + u0 + 4);
            u64t s0 = splat2(smem[R_RS + e * NN + ml]);
            u64t s1 = splat2(smem[R_RS + e * NN + ml + 32]);
            acc[0][0] = ffma2(acc[0][0], wA.x, s0); acc[0][1] = ffma2(acc[0][1], wA.y, s0);
            acc[0][2] = ffma2(acc[0][2], wB.x, s0); acc[0][3] = ffma2(acc[0][3], wB.y, s0);
            acc[1][0] = ffma2(acc[1][0], wA.x, s1); acc[1][1] = ffma2(acc[1][1], wA.y, s1);
            acc[1][2] = ffma2(acc[1][2], wB.x, s1); acc[1][3] = ffma2(acc[1][3], wB.y, s1);
        }
        {
            const float* nb0 = &smem[R_NODE + ml * NODE_PITCH];
            const float* nb1 = &smem[R_NODE + (ml + 32) * NODE_PITCH];
            #pragma unroll 2
            for (int f4 = 0; f4 < FF; f4 += 4) {
                float a0[4], a1[4];
                *(float4*)a0 = *(const float4*)(nb0 + f4);
                *(float4*)a1 = *(const float4*)(nb1 + f4);
                #pragma unroll
                for (int j = 0; j < 4; j++) {
                    const float* wr = V1 + (f4 + j) * U1C + u0;
                    ulonglong2 wA = *(const ulonglong2*)(wr);
                    ulonglong2 wB = *(const ulonglong2*)(wr + 4);
                    u64t s0 = splat2(a0[j]), s1 = splat2(a1[j]);
                    acc[0][0] = ffma2(acc[0][0], wA.x, s0); acc[0][1] = ffma2(acc[0][1], wA.y, s0);
                    acc[0][2] = ffma2(acc[0][2], wB.x, s0); acc[0][3] = ffma2(acc[0][3], wB.y, s0);
                    acc[1][0] = ffma2(acc[1][0], wA.x, s1); acc[1][1] = ffma2(acc[1][1], wA.y, s1);
                    acc[1][2] = ffma2(acc[1][2], wB.x, s1); acc[1][3] = ffma2(acc[1][3], wB.y, s1);
                }
            }
        }
        #pragma unroll
        for (int im = 0; im < 2; im++) {
            int m = ml + im * 32;
            float h[8];
            float2 x0 = unpack2(acc[im][0]), x1 = unpack2(acc[im][1]);
            float2 x2 = unpack2(acc[im][2]), x3 = unpack2(acc[im][3]);
            h[0] = tanhf(x0.x); h[1] = tanhf(x0.y); h[2] = tanhf(x1.x); h[3] = tanhf(x1.y);
            h[4] = tanhf(x2.x); h[5] = tanhf(x2.y); h[6] = tanhf(x3.x); h[7] = tanhf(x3.y);
            #pragma unroll
            for (int p = 0; p < 4; p++) {
                int k = u0 + 2 * p;
                *(u32t*)(smc + R_DAH * 4 + m * 336 + k * 2) = bfpair(h[2 * p], h[2 * p + 1]);
                *(u32t*)(smc + R_DAL * 4 + m * 336 + k * 2) =
                    bfpair(bflo(h[2 * p]), bflo(h[2 * p + 1]));
            }
        }
    }
    __syncthreads();

    // ---------------- Phase D: pre2 via mma.sync (bf16 hi/lo, 10 k-chunks) -----------------
    {
        const int e = wid >> 2, nb = wid & 3, n0 = nb * 16;
        float acc[8][4];
        #pragma unroll
        for (int j = 0; j < 8; j++) { acc[j][0] = acc[j][1] = acc[j][2] = acc[j][3] = 0.f; }
        const int al_r = (lane & 7) + ((lane >> 3) & 1) * 8;
        const int al_c8 = (lane >> 4) * 8;
        const u32t aHi = smb + R_DAH * 4 + (n0 + al_r) * 336;
        const u32t aLo = smb + R_DAL * 4 + (n0 + al_r) * 336;
        const int b_r = (lane & 7) + ((lane >> 4) << 3);
        const int b_k16 = ((lane >> 3) & 1) * 16;   // bytes within chunk row
        #pragma unroll 1
        for (int ck = 0; ck < 10; ck++) {
            const int k0 = ck * 16;
            for (int i = tid; i < 1024; i += NT) {
                int sp = i >> 9, j = i & 511, row = j >> 1, c8 = (j & 1) * 8;
                uint4 v = *(const uint4*)((const char*)g_W2pack
                              + (size_t)(sp * 256 + row) * 320 + (k0 + c8) * 2);
                *(uint4*)(smc + R_WCH * 4 + sp * 12288 + row * 48 + c8 * 2) = v;
            }
            __syncthreads();
            u32t ah0, ah1, ah2, ah3, al0, al1, al2, al3;
            LDSM_X4(ah0, ah1, ah2, ah3, aHi + (k0 + al_c8) * 2);
            LDSM_X4(al0, al1, al2, al3, aLo + (k0 + al_c8) * 2);
            #pragma unroll
            for (int t = 0; t < 4; t++) {
                u32t b0, b1, b2r, b3;
                LDSM_X4(b0, b1, b2r, b3,
                        smb + R_WCH * 4 + (e * 64 + t * 16 + b_r) * 48 + b_k16);
                MMA_BF16(acc[2 * t],     ah0, ah1, ah2, ah3, b0, b1);
                MMA_BF16(acc[2 * t + 1], ah0, ah1, ah2, ah3, b2r, b3);
                MMA_BF16(acc[2 * t],     al0, al1, al2, al3, b0, b1);
                MMA_BF16(acc[2 * t + 1], al0, al1, al2, al3, b2r, b3);
            }
            #pragma unroll
            for (int t = 0; t < 4; t++) {
                u32t b0, b1, b2r, b3;
                LDSM_X4(b0, b1, b2r, b3,
                        smb + R_WCH * 4 + 12288 + (e * 64 + t * 16 + b_r) * 48 + b_k16);
                MMA_BF16(acc[2 * t],     ah0, ah1, ah2, ah3, b0, b1);
                MMA_BF16(acc[2 * t + 1], ah0, ah1, ah2, ah3, b2r, b3);
            }
            __syncthreads();
        }
        // epilogue: write pre2 fp32 (+bias) over dead chunk region
        const int q = lane & 3, rw = lane >> 2;
        #pragma unroll
        for (int j = 0; j < 8; j++) {
            int u = 8 * j + 2 * q;
            float2 bb = *(const float2*)(b2 + e * 64 + u);
            int base = R_P2 + (e * 64 + n0 + rw) * P2_PITCH + u;
            smem[base]                    = acc[j][0] + bb.x;
            smem[base + 1]                = acc[j][1] + bb.y;
            smem[base + 8 * P2_PITCH]     = acc[j][2] + bb.x;
            smem[base + 8 * P2_PITCH + 1] = acc[j][3] + bb.y;
        }
    }
    __syncthreads();

    // ---------------- Phase E: h2 = tanh(sum_e adj_e@pre2_e + node@V2 + c2) -> F act tiles -
    {
        const int ml = lane, u0 = wid * 4;
        u64t acc[2][2];
        {
            ulonglong2 cA = *(const ulonglong2*)(c2 + u0);
            acc[0][0] = cA.x; acc[0][1] = cA.y;
            acc[1][0] = cA.x; acc[1][1] = cA.y;
        }
        #pragma unroll 1
        for (int e = 0; e < EM1; e++) {
            const float* adjb = &smem[R_ADJ + (e * NN + ml) * ADJ_PITCH];
            const float* p2b = &smem[R_P2 + e * NN * P2_PITCH + u0];
            #pragma unroll 4
            for (int n = 0; n < NN; n++) {
                ulonglong2 w = *(const ulonglong2*)(p2b + n * P2_PITCH);
                u64t s0 = splat2(adjb[n]);
                u64t s1 = splat2(adjb[32 * ADJ_PITCH + n]);
                acc[0][0] = ffma2(acc[0][0], w.x, s0); acc[0][1] = ffma2(acc[0][1], w.y, s0);
                acc[1][0] = ffma2(acc[1][0], w.x, s1); acc[1][1] = ffma2(acc[1][1], w.y, s1);
            }
        }
        {
            const float* nb0 = &smem[R_NODE + ml * NODE_PITCH];
            const float* nb1 = &smem[R_NODE + (ml + 32) * NODE_PITCH];
            #pragma unroll 2
            for (int f4 = 0; f4 < FF; f4 += 4) {
                float a0[4], a1[4];
                *(float4*)a0 = *(const float4*)(nb0 + f4);
                *(float4*)a1 = *(const float4*)(nb1 + f4);
                #pragma unroll
                for (int j = 0; j < 4; j++) {
                    ulonglong2 w = *(const ulonglong2*)(V2 + (f4 + j) * U2C + u0);
                    u64t s0 = splat2(a0[j]), s1 = splat2(a1[j]);
                    acc[0][0] = ffma2(acc[0][0], w.x, s0); acc[0][1] = ffma2(acc[0][1], w.y, s0);
                    acc[1][0] = ffma2(acc[1][0], w.x, s1); acc[1][1] = ffma2(acc[1][1], w.y, s1);
                }
            }
        }
        #pragma unroll
        for (int im = 0; im < 2; im++) {
            int m = ml + im * 32;
            float2 x0 = unpack2(acc[im][0]), x1 = unpack2(acc[im][1]);
            float t0 = tanhf(x0.x), t1 = tanhf(x0.y), t2 = tanhf(x1.x), t3 = tanhf(x1.y);
            *(u32t*)(smc + R_FAH * 4 + m * 224 + u0 * 2)       = bfpair(t0, t1);
            *(u32t*)(smc + R_FAH * 4 + m * 224 + (u0 + 2) * 2) = bfpair(t2, t3);
            *(u32t*)(smc + R_FAL * 4 + m * 224 + u0 * 2)       = bfpair(bflo(t0), bflo(t1));
            *(u32t*)(smc + R_FAL * 4 + m * 224 + (u0 + 2) * 2) = bfpair(bflo(t2), bflo(t3));
        }
        // F act tile cols 64..95 = node cols 0..31
        for (int idx = tid; idx < NN * 32; idx += NT) {
            int r = idx >> 5, k = 64 + (idx & 31);
            float v = smem[R_NODE + r * NODE_PITCH + (k - 64)];
            *(unsigned short*)(smc + R_FAH * 4 + r * 224 + k * 2) =
                __bfloat16_as_ushort(__float2bfloat16_rn(v));
            *(unsigned short*)(smc + R_FAL * 4 + r * 224 + k * 2) =
                __bfloat16_as_ushort(__float2bfloat16_rn(bflo(v)));
        }
    }
    __syncthreads();

    // ---------------- Phase F: gate pre-acts via mma.sync (6 k-chunks) ---------------------
    {
        const int uq = wid >> 2, nb = wid & 3, n0 = nb * 16;
        float acc[8][4];
        #pragma unroll
        for (int j = 0; j < 8; j++) { acc[j][0] = acc[j][1] = acc[j][2] = acc[j][3] = 0.f; }
        const int al_r = (lane & 7) + ((lane >> 3) & 1) * 8;
        const int al_c8 = (lane >> 4) * 8;
        const u32t aHi = smb + R_FAH * 4 + (n0 + al_r) * 224;
        const u32t aLo = smb + R_FAL * 4 + (n0 + al_r) * 224;
        const int b_r = (lane & 7) + ((lane >> 4) << 3);
        const int b_k16 = ((lane >> 3) & 1) * 16;
        #pragma unroll 1
        for (int ck = 0; ck < 6; ck++) {
            const int k0 = ck * 16;
            for (int i = tid; i < 1024; i += NT) {
                int sp = i >> 9, j = i & 511, row = j >> 1, c8 = (j & 1) * 8;
                uint4 v = *(const uint4*)((const char*)g_WGpack
                              + (size_t)(sp * 256 + row) * 192 + (k0 + c8) * 2);
                *(uint4*)(smc + R_WCH * 4 + sp * 12288 + row * 48 + c8 * 2) = v;
            }
            __syncthreads();
            u32t ah0, ah1, ah2, ah3, al0, al1, al2, al3;
            LDSM_X4(ah0, ah1, ah2, ah3, aHi + (k0 + al_c8) * 2);
            LDSM_X4(al0, al1, al2, al3, aLo + (k0 + al_c8) * 2);
            #pragma unroll
            for (int t = 0; t < 4; t++) {
                u32t b0, b1, b2r, b3;
                LDSM_X4(b0, b1, b2r, b3,
                        smb + R_WCH * 4 + (uq * 64 + t * 16 + b_r) * 48 + b_k16);
                MMA_BF16(acc[2 * t],     ah0, ah1, ah2, ah3, b0, b1);
                MMA_BF16(acc[2 * t + 1], ah0, ah1, ah2, ah3, b2r, b3);
                MMA_BF16(acc[2 * t],     al0, al1, al2, al3, b0, b1);
                MMA_BF16(acc[2 * t + 1], al0, al1, al2, al3, b2r, b3);
            }
            #pragma unroll
            for (int t = 0; t < 4; t++) {
                u32t b0, b1, b2r, b3;
                LDSM_X4(b0, b1, b2r, b3,
                        smb + R_WCH * 4 + 12288 + (uq * 64 + t * 16 + b_r) * 48 + b_k16);
                MMA_BF16(acc[2 * t],     ah0, ah1, ah2, ah3, b0, b1);
                MMA_BF16(acc[2 * t + 1], ah0, ah1, ah2, ah3, b2r, b3);
            }
            __syncthreads();
        }
        // epilogue: pi / pj fp32 (+bias) over dead chunk/pre2 region
        const int q = lane & 3, rw = lane >> 2;
        #pragma unroll
        for (int j = 0; j < 8; j++) {
            int up = uq * 64 + 8 * j + 2 * q;
            int mat = up >> 7, uu = up & 127;
            float2 bb = *(const float2*)((mat ? bj : bi) + uu);
            int base = (mat ? R_PJ : R_PI) + (n0 + rw) * PI_PITCH + uu;
            smem[base]                    = acc[j][0] + bb.x;
            smem[base + 1]                = acc[j][1] + bb.y;
            smem[base + 8 * PI_PITCH]     = acc[j][2] + bb.x;
            smem[base + 8 * PI_PITCH + 1] = acc[j][3] + bb.y;
        }
    }
    __syncthreads();

    // ---------------- Phase G: out[b][u] = tanh(sum_n sigmoid(pi)*tanh(pj)) ----------------
    {
        const int qg = tid >> 7, u = tid & 127;
        float s = 0.0f;
        #pragma unroll
        for (int i = 0; i < 16; i++) {
            int n = qg * 16 + i;
            float pi = smem[R_PI + n * PI_PITCH + u];
            float pj = smem[R_PJ + n * PI_PITCH + u];
            s += sigmoidf_(pi) * tanhf(pj);
        }
        smem[R_RED + qg * UAC + u] = s;
    }
    __syncthreads();
    if (tid < UAC) {
        float s = smem[R_RED + tid] + smem[R_RED + UAC + tid]
                + smem[R_RED + 2 * UAC + tid] + smem[R_RED + 3 * UAC + tid];
        out[(size_t)b * UAC + tid] = tanhf(s);
    }
}

extern "C" void kernel_launch(void* const* d_in, const int* in_sizes, int n_in,
                              void* d_out, int out_size) {
    (void)in_sizes; (void)n_in; (void)out_size;
    const float* adjacency = (const float*)d_in[0];
    const float* node = (const float*)d_in[2];
    const float* W1 = (const float*)d_in[3];
    const float* b1 = (const float*)d_in[4];
    const float* V1 = (const float*)d_in[5];
    const float* c1 = (const float*)d_in[6];
    const float* W2 = (const float*)d_in[7];
    const float* b2 = (const float*)d_in[8];
    const float* V2 = (const float*)d_in[9];
    const float* c2 = (const float*)d_in[10];
    const float* Wi = (const float*)d_in[11];
    const float* bi = (const float*)d_in[12];
    const float* Wj = (const float*)d_in[13];
    const float* bj = (const float*)d_in[14];

    preconv_kernel<<<256, 256>>>(W2, Wi, Wj);
    cudaFuncSetAttribute(encoder_kernel,
                         cudaFuncAttributeMaxDynamicSharedMemorySize, SMEM_BYTES);
    encoder_kernel<<<BATCH, NT, SMEM_BYTES>>>(adjacency, node,
                                              W1, b1, V1, c1,
                                              b2, V2, c2,
                                              bi, bj,
                                              (float*)d_out);
}

// round 13
// speedup vs baseline: 1.7084x; 1.2300x over previous
#include <cuda_runtime.h>
#include <cuda_bf16.h>
#include <math.h>
#include <cstdint>

typedef unsigned long long u64t;
typedef unsigned int u32t;

#define EM1 4
#define NN 64
#define FF 32
#define U1C 128
#define U2C 64
#define UAC 128
#define NT 512
#define BATCH 2048

#define ADJ_PITCH 65
#define NODE_PITCH 36
#define P2_PITCH 64
#define PI_PITCH 132

// ---- smem regions (float indices) ----
#define R_ADJ 0        // adj fp32 [4][64][65] = 16640   (A..E) ; after F-epi: pi@0, pj@8448
#define R_PI  0
#define R_PJ  8448
#define R_NODE 16640   // node fp32 [64][36] = 2304      (A..E)
#define R_RED 16896    // 512 (G; aliases dead node tail)
#define R_CAH 18944    // C A-tile hi bf16 [64 r][368B] = 5888 fl  (A/B..C) ; after C: F act tiles
#define R_CAL 24832    // C A-tile lo
#define R_FAH 18944    // F act hi bf16 [64][224B] = 3584 (E..F, aliases dead CA)
#define R_FAL 22528
#define R_DAH 30720    // D act hi bf16 [64][336B] = 5376 (A/C..D)
#define R_DAL 36096
#define R_P2  41472    // pre2 fp32 [256][64] = 16384 (D-epi..E) ; chunk buffers alias here
#define R_WCH 41472    // weight chunk buffer (C:12KB, D/F:24KB) — alive only mid-C/D/F
#define SMEM_FLOATS 57856
#define SMEM_BYTES (SMEM_FLOATS*4)   // 231424 B

// packed bf16 weights [split][row=u][k]
__device__ __align__(16) __nv_bfloat16 g_W2pack[2][256][160];  // D: row=e*64+u
__device__ __align__(16) __nv_bfloat16 g_WGpack[2][256][96];   // F: row=mat*128+u
__device__ __align__(16) __nv_bfloat16 g_W1pack[2][128][176];  // C: row=u, k=[W1|V1|b1|c1|0]

// ---- fp32x2 helpers ----
__device__ __forceinline__ u64t ffma2(u64t a, u64t w, u64t s) {
    u64t r; asm("fma.rn.f32x2 %0, %1, %2, %3;" : "=l"(r) : "l"(w), "l"(s), "l"(a)); return r;
}
__device__ __forceinline__ u64t splat2(float a) {
    u64t r; asm("mov.b64 %0, {%1, %1};" : "=l"(r) : "f"(a)); return r;
}
__device__ __forceinline__ float2 unpack2(u64t v) {
    float2 f; asm("mov.b64 {%0, %1}, %2;" : "=f"(f.x), "=f"(f.y) : "l"(v)); return f;
}
__device__ __forceinline__ float sigmoidf_(float x) { return 1.0f / (1.0f + expf(-x)); }

// ---- bf16 helpers ----
__device__ __forceinline__ u32t bfpair(float a, float b) {
    u32t lo = (u32t)__bfloat16_as_ushort(__float2bfloat16_rn(a));
    u32t hi = (u32t)__bfloat16_as_ushort(__float2bfloat16_rn(b));
    return lo | (hi << 16);
}
__device__ __forceinline__ float bflo(float x) { return x - __bfloat162float(__float2bfloat16_rn(x)); }
__device__ __forceinline__ unsigned short bfh(float x) {
    return __bfloat16_as_ushort(__float2bfloat16_rn(x));
}
__device__ __forceinline__ u32t smem_u32(const void* p) {
    u32t a; asm("{ .reg .u64 t; cvta.to.shared.u64 t, %1; cvt.u32.u64 %0, t; }" : "=r"(a) : "l"(p));
    return a;
}

#define LDSM_X4(r0, r1, r2, r3, addr) \
    asm volatile("ldmatrix.sync.aligned.m8n8.x4.shared.b16 {%0,%1,%2,%3}, [%4];" \
                 : "=r"(r0), "=r"(r1), "=r"(r2), "=r"(r3) : "r"(addr))

#define MMA_BF16(c, a0, a1, a2, a3, b0, b1) \
    asm volatile("mma.sync.aligned.m16n8k16.row.col.f32.bf16.bf16.f32 " \
                 "{%0,%1,%2,%3}, {%4,%5,%6,%7}, {%8,%9}, {%0,%1,%2,%3};" \
                 : "+f"((c)[0]), "+f"((c)[1]), "+f"((c)[2]), "+f"((c)[3]) \
                 : "r"(a0), "r"(a1), "r"(a2), "r"(a3), "r"(b0), "r"(b1))

// ---- weight preconversion ----
__global__ void preconv_kernel(const float* __restrict__ W2,
                               const float* __restrict__ Wi,
                               const float* __restrict__ Wj,
                               const float* __restrict__ W1,
                               const float* __restrict__ V1,
                               const float* __restrict__ b1,
                               const float* __restrict__ c1) {
    int i = blockIdx.x * 256 + threadIdx.x;
    if (i < 256 * 160) {
        int row = i / 160, k = i % 160;
        int e = row >> 6, u = row & 63;
        float w = W2[(e * 160 + k) * 64 + u];
        __nv_bfloat16 h = __float2bfloat16_rn(w);
        g_W2pack[0][row][k] = h;
        g_W2pack[1][row][k] = __float2bfloat16_rn(w - __bfloat162float(h));
    } else if (i < 256 * 160 + 256 * 96) {
        int j = i - 256 * 160;
        int row = j / 96, k = j % 96;
        int mat = row >> 7, u = row & 127;
        float w = (mat ? Wj : Wi)[k * 128 + u];
        __nv_bfloat16 h = __float2bfloat16_rn(w);
        g_WGpack[0][row][k] = h;
        g_WGpack[1][row][k] = __float2bfloat16_rn(w - __bfloat162float(h));
    } else if (i < 256 * 160 + 256 * 96 + 128 * 176) {
        int j = i - (256 * 160 + 256 * 96);
        int u = j / 176, k = j % 176;
        float w;
        if (k < 128)      w = W1[k * 128 + u];          // k = e*32+f
        else if (k < 160) w = V1[(k - 128) * 128 + u];
        else if (k < 164) w = b1[(k - 160) * 128 + u];
        else if (k == 164) w = c1[u];
        else              w = 0.0f;
        __nv_bfloat16 h = __float2bfloat16_rn(w);
        g_W1pack[0][u][k] = h;
        g_W1pack[1][u][k] = __float2bfloat16_rn(w - __bfloat162float(h));
    }
}

__global__ void __launch_bounds__(NT, 1)
encoder_kernel(const float* __restrict__ adjacency,
               const float* __restrict__ node,
               const float* __restrict__ b2, const float* __restrict__ V2,
               const float* __restrict__ c2,
               const float* __restrict__ bi, const float* __restrict__ bj,
               float* __restrict__ out)
{
    extern __shared__ float smem[];
    char* smc = (char*)smem;
    const int b = blockIdx.x;
    const int tid = threadIdx.x;
    const int wid = tid >> 5;
    const int lane = tid & 31;
    const u32t smb = smem_u32(smem);

    // ---------------- Phase A: stage adj + node; node bf16 into C/D act tiles; zero pads --
    {
        const float* adjB = adjacency + (size_t)b * (NN * NN * 5);
        for (int idx = tid; idx < NN * NN * 5; idx += NT) {
            float v = adjB[idx];
            int e = idx % 5;
            int r = idx / 5;
            if (e > 0)
                smem[R_ADJ + ((e - 1) * NN + (r >> 6)) * ADJ_PITCH + (r & 63)] = v;
        }
        const float* nodeB = node + (size_t)b * (NN * FF);
        for (int idx = tid; idx < NN * FF; idx += NT) {
            int r = idx >> 5, f = idx & 31;
            float v = nodeB[idx];
            smem[R_NODE + r * NODE_PITCH + f] = v;
            unsigned short h = bfh(v), l = bfh(bflo(v));
            *(unsigned short*)(smc + R_CAH * 4 + r * 368 + (128 + f) * 2) = h;
            *(unsigned short*)(smc + R_CAL * 4 + r * 368 + (128 + f) * 2) = l;
            *(unsigned short*)(smc + R_DAH * 4 + r * 336 + (128 + f) * 2) = h;
            *(unsigned short*)(smc + R_DAL * 4 + r * 336 + (128 + f) * 2) = l;
        }
        // zero C A-tile pad cols 160..175 (both splits); B overwrites 160..164
        for (int idx = tid; idx < 1024; idx += NT) {
            int sp = idx >> 9, j = idx & 511, r = j >> 3, o = (j & 7) * 4;
            *(u32t*)(smc + (sp ? R_CAL : R_CAH) * 4 + r * 368 + 320 + o) = 0;
        }
    }
    __syncthreads();

    // ---------------- Phase B: an = adj_e @ node -> C A-tile bf16 ; rs, const cols --------
    {
        const int e = wid >> 2, fs = wid & 3, f0 = fs * 8;
        u64t acc[2][4];
        #pragma unroll
        for (int mh = 0; mh < 2; mh++)
            #pragma unroll
            for (int j = 0; j < 4; j++) acc[mh][j] = 0ull;
        float rs0 = 0.f, rs1 = 0.f;
        const float* a0p = &smem[R_ADJ + (e * NN + lane) * ADJ_PITCH];
        const float* a1p = a0p + 32 * ADJ_PITCH;
        const float* np = &smem[R_NODE + f0];
        #pragma unroll 4
        for (int n = 0; n < NN; n++) {
            float a0 = a0p[n], a1 = a1p[n];
            rs0 += a0; rs1 += a1;
            u64t s0 = splat2(a0), s1 = splat2(a1);
            ulonglong2 v0 = *(const ulonglong2*)(np + n * NODE_PITCH);
            ulonglong2 v1 = *(const ulonglong2*)(np + n * NODE_PITCH + 4);
            acc[0][0] = ffma2(acc[0][0], v0.x, s0); acc[0][1] = ffma2(acc[0][1], v0.y, s0);
            acc[0][2] = ffma2(acc[0][2], v1.x, s0); acc[0][3] = ffma2(acc[0][3], v1.y, s0);
            acc[1][0] = ffma2(acc[1][0], v0.x, s1); acc[1][1] = ffma2(acc[1][1], v0.y, s1);
            acc[1][2] = ffma2(acc[1][2], v1.x, s1); acc[1][3] = ffma2(acc[1][3], v1.y, s1);
        }
        #pragma unroll
        for (int mh = 0; mh < 2; mh++) {
            int m = lane + mh * 32;
            float a[8];
            float2 x0 = unpack2(acc[mh][0]), x1 = unpack2(acc[mh][1]);
            float2 x2 = unpack2(acc[mh][2]), x3 = unpack2(acc[mh][3]);
            a[0] = x0.x; a[1] = x0.y; a[2] = x1.x; a[3] = x1.y;
            a[4] = x2.x; a[5] = x2.y; a[6] = x3.x; a[7] = x3.y;
            #pragma unroll
            for (int p = 0; p < 4; p++) {
                int k = e * 32 + f0 + 2 * p;
                *(u32t*)(smc + R_CAH * 4 + m * 368 + k * 2) = bfpair(a[2 * p], a[2 * p + 1]);
                *(u32t*)(smc + R_CAL * 4 + m * 368 + k * 2) =
                    bfpair(bflo(a[2 * p]), bflo(a[2 * p + 1]));
            }
        }
        if (fs == 0) {
            #pragma unroll
            for (int mh = 0; mh < 2; mh++) {
                int m = lane + mh * 32;
                float rs = mh ? rs1 : rs0;
                *(unsigned short*)(smc + R_CAH * 4 + m * 368 + (160 + e) * 2) = bfh(rs);
                *(unsigned short*)(smc + R_CAL * 4 + m * 368 + (160 + e) * 2) = bfh(bflo(rs));
                if (e == 0) {   // const-1 column
                    *(unsigned short*)(smc + R_CAH * 4 + m * 368 + 164 * 2) = 0x3F80;
                    *(unsigned short*)(smc + R_CAL * 4 + m * 368 + 164 * 2) = 0;
                }
            }
        }
    }
    __syncthreads();

    // ---------------- Phase C: h1 via mma.sync (11 k-chunks, prefetched) -> D act tiles ---
    {
        const int mb = wid & 3, m0 = mb * 16;
        const int us = wid >> 2, u0 = us * 32;
        float acc[4][4];
        #pragma unroll
        for (int j = 0; j < 4; j++) { acc[j][0] = acc[j][1] = acc[j][2] = acc[j][3] = 0.f; }
        const int al_r = (lane & 7) + ((lane >> 3) & 1) * 8;
        const int al_c8 = (lane >> 4) * 8;
        const u32t aHi = smb + R_CAH * 4 + (m0 + al_r) * 368;
        const u32t aLo = smb + R_CAL * 4 + (m0 + al_r) * 368;
        const int b_r = (lane & 7) + ((lane >> 4) << 3);
        const int b_k16 = ((lane >> 3) & 1) * 16;
        // staging: 1 uint4 per thread per chunk (FIX: generic pointer, not shared-window u32)
        const int s_sp = tid >> 8, s_row = (tid & 255) >> 1, s_c8 = (tid & 1) * 8;
        const char* s_src = (const char*)g_W1pack + (size_t)(s_sp * 128 + s_row) * 352 + s_c8 * 2;
        char* s_dst = smc + R_WCH * 4 + s_sp * 6144 + s_row * 48 + s_c8 * 2;
        uint4 pf = *(const uint4*)(s_src);
        #pragma unroll 1
        for (int ck = 0; ck < 11; ck++) {
            *(uint4*)s_dst = pf;
            __syncthreads();
            if (ck < 10) pf = *(const uint4*)(s_src + (ck + 1) * 32);
            const int k0 = ck * 16;
            u32t ah0, ah1, ah2, ah3, al0, al1, al2, al3;
            LDSM_X4(ah0, ah1, ah2, ah3, aHi + (k0 + al_c8) * 2);
            LDSM_X4(al0, al1, al2, al3, aLo + (k0 + al_c8) * 2);
            #pragma unroll
            for (int t = 0; t < 2; t++) {
                u32t b0, b1, b2r, b3;
                LDSM_X4(b0, b1, b2r, b3,
                        smb + R_WCH * 4 + (u0 + t * 16 + b_r) * 48 + b_k16);
                MMA_BF16(acc[2 * t],     ah0, ah1, ah2, ah3, b0, b1);
                MMA_BF16(acc[2 * t + 1], ah0, ah1, ah2, ah3, b2r, b3);
                MMA_BF16(acc[2 * t],     al0, al1, al2, al3, b0, b1);
                MMA_BF16(acc[2 * t + 1], al0, al1, al2, al3, b2r, b3);
            }
            #pragma unroll
            for (int t = 0; t < 2; t++) {
                u32t b0, b1, b2r, b3;
                LDSM_X4(b0, b1, b2r, b3,
                        smb + R_WCH * 4 + 6144 + (u0 + t * 16 + b_r) * 48 + b_k16);
                MMA_BF16(acc[2 * t],     ah0, ah1, ah2, ah3, b0, b1);
                MMA_BF16(acc[2 * t + 1], ah0, ah1, ah2, ah3, b2r, b3);
            }
            __syncthreads();
        }
        // epilogue: h1 = tanh(acc) -> D act tiles (cols 0..127)
        const int q = lane & 3, rw = lane >> 2;
        #pragma unroll
        for (int j = 0; j < 4; j++) {
            int u = u0 + 8 * j + 2 * q;
            #pragma unroll
            for (int h = 0; h < 2; h++) {
                int m = m0 + rw + 8 * h;
                float t0 = tanhf(acc[j][2 * h]), t1 = tanhf(acc[j][2 * h + 1]);
                *(u32t*)(smc + R_DAH * 4 + m * 336 + u * 2) = bfpair(t0, t1);
                *(u32t*)(smc + R_DAL * 4 + m * 336 + u * 2) = bfpair(bflo(t0), bflo(t1));
            }
        }
    }
    __syncthreads();

    // ---------------- Phase D: pre2 via mma.sync (10 k-chunks, prefetched) ----------------
    {
        const int e = wid >> 2, nb = wid & 3, n0 = nb * 16;
        float acc[8][4];
        #pragma unroll
        for (int j = 0; j < 8; j++) { acc[j][0] = acc[j][1] = acc[j][2] = acc[j][3] = 0.f; }
        const int al_r = (lane & 7) + ((lane >> 3) & 1) * 8;
        const int al_c8 = (lane >> 4) * 8;
        const u32t aHi = smb + R_DAH * 4 + (n0 + al_r) * 336;
        const u32t aLo = smb + R_DAL * 4 + (n0 + al_r) * 336;
        const int b_r = (lane & 7) + ((lane >> 4) << 3);
        const int b_k16 = ((lane >> 3) & 1) * 16;
        const int i0 = tid, i1 = tid + 512;
        const int sp0 = i0 >> 9, j0 = i0 & 511, row0 = j0 >> 1, c80 = (j0 & 1) * 8;
        const int sp1 = i1 >> 9, j1 = i1 & 511, row1 = j1 >> 1, c81 = (j1 & 1) * 8;
        const char* src0 = (const char*)g_W2pack + (size_t)(sp0 * 256 + row0) * 320 + c80 * 2;
        const char* src1 = (const char*)g_W2pack + (size_t)(sp1 * 256 + row1) * 320 + c81 * 2;
        char* dst0 = smc + R_WCH * 4 + sp0 * 12288 + row0 * 48 + c80 * 2;
        char* dst1 = smc + R_WCH * 4 + sp1 * 12288 + row1 * 48 + c81 * 2;
        uint4 pf0 = *(const uint4*)(src0);
        uint4 pf1 = *(const uint4*)(src1);
        #pragma unroll 1
        for (int ck = 0; ck < 10; ck++) {
            *(uint4*)dst0 = pf0;
            *(uint4*)dst1 = pf1;
            __syncthreads();
            if (ck < 9) {
                pf0 = *(const uint4*)(src0 + (ck + 1) * 32);
                pf1 = *(const uint4*)(src1 + (ck + 1) * 32);
            }
            const int k0 = ck * 16;
            u32t ah0, ah1, ah2, ah3, al0, al1, al2, al3;
            LDSM_X4(ah0, ah1, ah2, ah3, aHi + (k0 + al_c8) * 2);
            LDSM_X4(al0, al1, al2, al3, aLo + (k0 + al_c8) * 2);
            #pragma unroll
            for (int t = 0; t < 4; t++) {
                u32t b0, b1, b2r, b3;
                LDSM_X4(b0, b1, b2r, b3,
                        smb + R_WCH * 4 + (e * 64 + t * 16 + b_r) * 48 + b_k16);
                MMA_BF16(acc[2 * t],     ah0, ah1, ah2, ah3, b0, b1);
                MMA_BF16(acc[2 * t + 1], ah0, ah1, ah2, ah3, b2r, b3);
                MMA_BF16(acc[2 * t],     al0, al1, al2, al3, b0, b1);
                MMA_BF16(acc[2 * t + 1], al0, al1, al2, al3, b2r, b3);
            }
            #pragma unroll
            for (int t = 0; t < 4; t++) {
                u32t b0, b1, b2r, b3;
                LDSM_X4(b0, b1, b2r, b3,
                        smb + R_WCH * 4 + 12288 + (e * 64 + t * 16 + b_r) * 48 + b_k16);
                MMA_BF16(acc[2 * t],     ah0, ah1, ah2, ah3, b0, b1);
                MMA_BF16(acc[2 * t + 1], ah0, ah1, ah2, ah3, b2r, b3);
            }
            __syncthreads();
        }
        // epilogue: pre2 fp32 (+bias) overwrites chunk region
        const int q = lane & 3, rw = lane >> 2;
        #pragma unroll
        for (int j = 0; j < 8; j++) {
            int u = 8 * j + 2 * q;
            float2 bb = *(const float2*)(b2 + e * 64 + u);
            int base = R_P2 + (e * 64 + n0 + rw) * P2_PITCH + u;
            smem[base]                    = acc[j][0] + bb.x;
            smem[base + 1]                = acc[j][1] + bb.y;
            smem[base + 8 * P2_PITCH]     = acc[j][2] + bb.x;
            smem[base + 8 * P2_PITCH + 1] = acc[j][3] + bb.y;
        }
    }
    __syncthreads();

    // ---------------- Phase E: h2 = tanh(sum_e adj_e@pre2_e + node@V2 + c2) -> F act tiles -
    {
        const int ml = lane, u0 = wid * 4;
        u64t acc[2][2];
        {
            ulonglong2 cA = *(const ulonglong2*)(c2 + u0);
            acc[0][0] = cA.x; acc[0][1] = cA.y;
            acc[1][0] = cA.x; acc[1][1] = cA.y;
        }
        #pragma unroll 1
        for (int e = 0; e < EM1; e++) {
            const float* adjb = &smem[R_ADJ + (e * NN + ml) * ADJ_PITCH];
            const float* p2b = &smem[R_P2 + e * NN * P2_PITCH + u0];
            #pragma unroll 4
            for (int n = 0; n < NN; n++) {
                ulonglong2 w = *(const ulonglong2*)(p2b + n * P2_PITCH);
                u64t s0 = splat2(adjb[n]);
                u64t s1 = splat2(adjb[32 * ADJ_PITCH + n]);
                acc[0][0] = ffma2(acc[0][0], w.x, s0); acc[0][1] = ffma2(acc[0][1], w.y, s0);
                acc[1][0] = ffma2(acc[1][0], w.x, s1); acc[1][1] = ffma2(acc[1][1], w.y, s1);
            }
        }
        {
            const float* nb0 = &smem[R_NODE + ml * NODE_PITCH];
            const float* nb1 = &smem[R_NODE + (ml + 32) * NODE_PITCH];
            #pragma unroll 2
            for (int f4 = 0; f4 < FF; f4 += 4) {
                float a0[4], a1[4];
                *(float4*)a0 = *(const float4*)(nb0 + f4);
                *(float4*)a1 = *(const float4*)(nb1 + f4);
                #pragma unroll
                for (int j = 0; j < 4; j++) {
                    ulonglong2 w = *(const ulonglong2*)(V2 + (f4 + j) * U2C + u0);
                    u64t s0 = splat2(a0[j]), s1 = splat2(a1[j]);
                    acc[0][0] = ffma2(acc[0][0], w.x, s0); acc[0][1] = ffma2(acc[0][1], w.y, s0);
                    acc[1][0] = ffma2(acc[1][0], w.x, s1); acc[1][1] = ffma2(acc[1][1], w.y, s1);
                }
            }
        }
        #pragma unroll
        for (int im = 0; im < 2; im++) {
            int m = ml + im * 32;
            float2 x0 = unpack2(acc[im][0]), x1 = unpack2(acc[im][1]);
            float t0 = tanhf(x0.x), t1 = tanhf(x0.y), t2 = tanhf(x1.x), t3 = tanhf(x1.y);
            *(u32t*)(smc + R_FAH * 4 + m * 224 + u0 * 2)       = bfpair(t0, t1);
            *(u32t*)(smc + R_FAH * 4 + m * 224 + (u0 + 2) * 2) = bfpair(t2, t3);
            *(u32t*)(smc + R_FAL * 4 + m * 224 + u0 * 2)       = bfpair(bflo(t0), bflo(t1));
            *(u32t*)(smc + R_FAL * 4 + m * 224 + (u0 + 2) * 2) = bfpair(bflo(t2), bflo(t3));
        }
        // F act tile cols 64..95 = node
        for (int idx = tid; idx < NN * 32; idx += NT) {
            int r = idx >> 5, k = 64 + (idx & 31);
            float v = smem[R_NODE + r * NODE_PITCH + (k - 64)];
            *(unsigned short*)(smc + R_FAH * 4 + r * 224 + k * 2) = bfh(v);
            *(unsigned short*)(smc + R_FAL * 4 + r * 224 + k * 2) = bfh(bflo(v));
        }
    }
    __syncthreads();

    // ---------------- Phase F: gate pre-acts via mma.sync (6 k-chunks, prefetched) --------
    {
        const int uq = wid >> 2, nb = wid & 3, n0 = nb * 16;
        float acc[8][4];
        #pragma unroll
        for (int j = 0; j < 8; j++) { acc[j][0] = acc[j][1] = acc[j][2] = acc[j][3] = 0.f; }
        const int al_r = (lane & 7) + ((lane >> 3) & 1) * 8;
        const int al_c8 = (lane >> 4) * 8;
        const u32t aHi = smb + R_FAH * 4 + (n0 + al_r) * 224;
        const u32t aLo = smb + R_FAL * 4 + (n0 + al_r) * 224;
        const int b_r = (lane & 7) + ((lane >> 4) << 3);
        const int b_k16 = ((lane >> 3) & 1) * 16;
        const int i0 = tid, i1 = tid + 512;
        const int sp0 = i0 >> 9, j0 = i0 & 511, row0 = j0 >> 1, c80 = (j0 & 1) * 8;
        const int sp1 = i1 >> 9, j1 = i1 & 511, row1 = j1 >> 1, c81 = (j1 & 1) * 8;
        const char* src0 = (const char*)g_WGpack + (size_t)(sp0 * 256 + row0) * 192 + c80 * 2;
        const char* src1 = (const char*)g_WGpack + (size_t)(sp1 * 256 + row1) * 192 + c81 * 2;
        char* dst0 = smc + R_WCH * 4 + sp0 * 12288 + row0 * 48 + c80 * 2;
        char* dst1 = smc + R_WCH * 4 + sp1 * 12288 + row1 * 48 + c81 * 2;
        uint4 pf0 = *(const uint4*)(src0);
        uint4 pf1 = *(const uint4*)(src1);
        #pragma unroll 1
        for (int ck = 0; ck < 6; ck++) {
            *(uint4*)dst0 = pf0;
            *(uint4*)dst1 = pf1;
            __syncthreads();
            if (ck < 5) {
                pf0 = *(const uint4*)(src0 + (ck + 1) * 32);
                pf1 = *(const uint4*)(src1 + (ck + 1) * 32);
            }
            const int k0 = ck * 16;
            u32t ah0, ah1, ah2, ah3, al0, al1, al2, al3;
            LDSM_X4(ah0, ah1, ah2, ah3, aHi + (k0 + al_c8) * 2);
            LDSM_X4(al0, al1, al2, al3, aLo + (k0 + al_c8) * 2);
            #pragma unroll
            for (int t = 0; t < 4; t++) {
                u32t b0, b1, b2r, b3;
                LDSM_X4(b0, b1, b2r, b3,
                        smb + R_WCH * 4 + (uq * 64 + t * 16 + b_r) * 48 + b_k16);
                MMA_BF16(acc[2 * t],     ah0, ah1, ah2, ah3, b0, b1);
                MMA_BF16(acc[2 * t + 1], ah0, ah1, ah2, ah3, b2r, b3);
                MMA_BF16(acc[2 * t],     al0, al1, al2, al3, b0, b1);
                MMA_BF16(acc[2 * t + 1], al0, al1, al2, al3, b2r, b3);
            }
            #pragma unroll
            for (int t = 0; t < 4; t++) {
                u32t b0, b1, b2r, b3;
                LDSM_X4(b0, b1, b2r, b3,
                        smb + R_WCH * 4 + 12288 + (uq * 64 + t * 16 + b_r) * 48 + b_k16);
                MMA_BF16(acc[2 * t],     ah0, ah1, ah2, ah3, b0, b1);
                MMA_BF16(acc[2 * t + 1], ah0, ah1, ah2, ah3, b2r, b3);
            }
            __syncthreads();
        }
        // epilogue: pi/pj (+bias) over dead adj region
        const int q = lane & 3, rw = lane >> 2;
        #pragma unroll
        for (int j = 0; j < 8; j++) {
            int up = uq * 64 + 8 * j + 2 * q;
            int mat = up >> 7, uu = up & 127;
            float2 bb = *(const float2*)((mat ? bj : bi) + uu);
            int base = (mat ? R_PJ : R_PI) + (n0 + rw) * PI_PITCH + uu;
            smem[base]                    = acc[j][0] + bb.x;
            smem[base + 1]                = acc[j][1] + bb.y;
            smem[base + 8 * PI_PITCH]     = acc[j][2] + bb.x;
            smem[base + 8 * PI_PITCH + 1] = acc[j][3] + bb.y;
        }
    }
    __syncthreads();

    // ---------------- Phase G: out[b][u] = tanh(sum_n sigmoid(pi)*tanh(pj)) ----------------
    {
        const int qg = tid >> 7, u = tid & 127;
        float s = 0.0f;
        #pragma unroll
        for (int i = 0; i < 16; i++) {
            int n = qg * 16 + i;
            float pi = smem[R_PI + n * PI_PITCH + u];
            float pj = smem[R_PJ + n * PI_PITCH + u];
            s += sigmoidf_(pi) * tanhf(pj);
        }
        smem[R_RED + qg * UAC + u] = s;
    }
    __syncthreads();
    if (tid < UAC) {
        float s = smem[R_RED + tid] + smem[R_RED + UAC + tid]
                + smem[R_RED + 2 * UAC + tid] + smem[R_RED + 3 * UAC + tid];
        out[(size_t)b * UAC + tid] = tanhf(s);
    }
}

extern "C" void kernel_launch(void* const* d_in, const int* in_sizes, int n_in,
                              void* d_out, int out_size) {
    (void)in_sizes; (void)n_in; (void)out_size;
    const float* adjacency = (const float*)d_in[0];
    const float* node = (const float*)d_in[2];
    const float* W1 = (const float*)d_in[3];
    const float* b1 = (const float*)d_in[4];
    const float* V1 = (const float*)d_in[5];
    const float* c1 = (const float*)d_in[6];
    const float* W2 = (const float*)d_in[7];
    const float* b2 = (const float*)d_in[8];
    const float* V2 = (const float*)d_in[9];
    const float* c2 = (const float*)d_in[10];
    const float* Wi = (const float*)d_in[11];
    const float* bi = (const float*)d_in[12];
    const float* Wj = (const float*)d_in[13];
    const float* bj = (const float*)d_in[14];

    preconv_kernel<<<344, 256>>>(W2, Wi, Wj, W1, V1, b1, c1);
    cudaFuncSetAttribute(encoder_kernel,
                         cudaFuncAttributeMaxDynamicSharedMemorySize, SMEM_BYTES);
    encoder_kernel<<<BATCH, NT, SMEM_BYTES>>>(adjacency, node,
                                              b2, V2, c2,
                                              bi, bj,
                                              (float*)d_out);
}

// round 14
// speedup vs baseline: 1.9588x; 1.1466x over previous
#include <cuda_runtime.h>
#include <cuda_bf16.h>
#include <math.h>
#include <cstdint>

typedef unsigned long long u64t;
typedef unsigned int u32t;

#define EM1 4
#define NN 64
#define FF 32
#define U1C 128
#define U2C 64
#define UAC 128
#define NT 512
#define BATCH 2048

#define NODE_PITCH 36
#define PI_PITCH 132

// ---- smem regions (float indices) ----
// AB: adjacency bf16 A-tiles [64m][264 cols, pitch 528B], cols n'=e*64+n (0..255)
#define R_AB_H 0       // 8448 fl          (A..E) ; after E: pi/pj alias here
#define R_AB_L 8448    // 8448 fl -> 16896
#define R_PI   0       // pi [64][132] (F-epi..G)
#define R_PJ   8448    // pj [64][132]
#define R_NODE 16896   // node fp32 [64][36] = 2304 -> 19200
#define R_RED  19200   // 512 -> 19712
#define R_CAH  19712   // C A-tile hi bf16 [64][368B] = 5888 fl (B..C; then h1 in place for D)
#define R_CAL  25600   // 5888 -> 31488
#define R_FAH  19712   // F act hi [64][224B] = 3584 (E..F, aliases dead CA)
#define R_FAL  23296   // -> 26880
#define R_PTH  31488   // pre2T hi bf16 [64u][528B] = 8448 fl (D-epi..E)
#define R_PTL  39936   // 8448 -> 48384
#define R_WCH  31488   // weight chunk buffer (C:12KB, D/F:24KB) aliases PT (timeline-disjoint)
#define SMEM_FLOATS 48384
#define SMEM_BYTES (SMEM_FLOATS*4)   // 193536 B

// packed bf16 weights [split][row=u][k]
__device__ __align__(16) __nv_bfloat16 g_W2pack[2][256][160];  // D: row=e*64+u
__device__ __align__(16) __nv_bfloat16 g_WGpack[2][256][96];   // F: row=mat*128+u
__device__ __align__(16) __nv_bfloat16 g_W1pack[2][128][176];  // C: row=u, k=[W1|V1|b1|c1|0]

// ---- fp32x2 helpers ----
__device__ __forceinline__ u64t ffma2(u64t a, u64t w, u64t s) {
    u64t r; asm("fma.rn.f32x2 %0, %1, %2, %3;" : "=l"(r) : "l"(w), "l"(s), "l"(a)); return r;
}
__device__ __forceinline__ u64t splat2(float a) {
    u64t r; asm("mov.b64 %0, {%1, %1};" : "=l"(r) : "f"(a)); return r;
}
__device__ __forceinline__ float2 unpack2(u64t v) {
    float2 f; asm("mov.b64 {%0, %1}, %2;" : "=f"(f.x), "=f"(f.y) : "l"(v)); return f;
}
__device__ __forceinline__ float sigmoidf_(float x) { return 1.0f / (1.0f + expf(-x)); }

// ---- bf16 helpers ----
__device__ __forceinline__ u32t bfpair(float a, float b) {
    u32t lo = (u32t)__bfloat16_as_ushort(__float2bfloat16_rn(a));
    u32t hi = (u32t)__bfloat16_as_ushort(__float2bfloat16_rn(b));
    return lo | (hi << 16);
}
__device__ __forceinline__ float bflo(float x) { return x - __bfloat162float(__float2bfloat16_rn(x)); }
__device__ __forceinline__ unsigned short bfh(float x) {
    return __bfloat16_as_ushort(__float2bfloat16_rn(x));
}
__device__ __forceinline__ u32t smem_u32(const void* p) {
    u32t a; asm("{ .reg .u64 t; cvta.to.shared.u64 t, %1; cvt.u32.u64 %0, t; }" : "=r"(a) : "l"(p));
    return a;
}

#define LDSM_X4(r0, r1, r2, r3, addr) \
    asm volatile("ldmatrix.sync.aligned.m8n8.x4.shared.b16 {%0,%1,%2,%3}, [%4];" \
                 : "=r"(r0), "=r"(r1), "=r"(r2), "=r"(r3) : "r"(addr))

#define MMA_BF16(c, a0, a1, a2, a3, b0, b1) \
    asm volatile("mma.sync.aligned.m16n8k16.row.col.f32.bf16.bf16.f32 " \
                 "{%0,%1,%2,%3}, {%4,%5,%6,%7}, {%8,%9}, {%0,%1,%2,%3};" \
                 : "+f"((c)[0]), "+f"((c)[1]), "+f"((c)[2]), "+f"((c)[3]) \
                 : "r"(a0), "r"(a1), "r"(a2), "r"(a3), "r"(b0), "r"(b1))

// ---- weight preconversion ----
__global__ void preconv_kernel(const float* __restrict__ W2,
                               const float* __restrict__ Wi,
                               const float* __restrict__ Wj,
                               const float* __restrict__ W1,
                               const float* __restrict__ V1,
                               const float* __restrict__ b1,
                               const float* __restrict__ c1) {
    int i = blockIdx.x * 256 + threadIdx.x;
    if (i < 256 * 160) {
        int row = i / 160, k = i % 160;
        int e = row >> 6, u = row & 63;
        float w = W2[(e * 160 + k) * 64 + u];
        __nv_bfloat16 h = __float2bfloat16_rn(w);
        g_W2pack[0][row][k] = h;
        g_W2pack[1][row][k] = __float2bfloat16_rn(w - __bfloat162float(h));
    } else if (i < 256 * 160 + 256 * 96) {
        int j = i - 256 * 160;
        int row = j / 96, k = j % 96;
        int mat = row >> 7, u = row & 127;
        float w = (mat ? Wj : Wi)[k * 128 + u];
        __nv_bfloat16 h = __float2bfloat16_rn(w);
        g_WGpack[0][row][k] = h;
        g_WGpack[1][row][k] = __float2bfloat16_rn(w - __bfloat162float(h));
    } else if (i < 256 * 160 + 256 * 96 + 128 * 176) {
        int j = i - (256 * 160 + 256 * 96);
        int u = j / 176, k = j % 176;
        float w;
        if (k < 128)      w = W1[k * 128 + u];
        else if (k < 160) w = V1[(k - 128) * 128 + u];
        else if (k < 164) w = b1[(k - 160) * 128 + u];
        else if (k == 164) w = c1[u];
        else              w = 0.0f;
        __nv_bfloat16 h = __float2bfloat16_rn(w);
        g_W1pack[0][u][k] = h;
        g_W1pack[1][u][k] = __float2bfloat16_rn(w - __bfloat162float(h));
    }
}

__global__ void __launch_bounds__(NT, 1)
encoder_kernel(const float* __restrict__ adjacency,
               const float* __restrict__ node,
               const float* __restrict__ b2, const float* __restrict__ V2,
               const float* __restrict__ c2,
               const float* __restrict__ bi, const float* __restrict__ bj,
               float* __restrict__ out)
{
    extern __shared__ float smem[];
    char* smc = (char*)smem;
    const int b = blockIdx.x;
    const int tid = threadIdx.x;
    const int wid = tid >> 5;
    const int lane = tid & 31;
    const u32t smb = smem_u32(smem);

    // ---------------- Phase A: adjacency -> bf16 hi/lo A-tiles; node fp32 + bf16 cols ----
    {
        const float* adjB = adjacency + (size_t)b * (NN * NN * 5);
        for (int idx = tid; idx < NN * NN * 5; idx += NT) {
            float v = adjB[idx];
            int e = idx % 5;
            int r = idx / 5;
            if (e > 0) {
                int m = r >> 6, n = r & 63;
                int col = (e - 1) * 64 + n;
                *(unsigned short*)(smc + R_AB_H * 4 + m * 528 + col * 2) = bfh(v);
                *(unsigned short*)(smc + R_AB_L * 4 + m * 528 + col * 2) = bfh(bflo(v));
            }
        }
        const float* nodeB = node + (size_t)b * (NN * FF);
        for (int idx = tid; idx < NN * FF; idx += NT) {
            int r = idx >> 5, f = idx & 31;
            float v = nodeB[idx];
            smem[R_NODE + r * NODE_PITCH + f] = v;
            // C A-tile cols 128..159 (these also serve as D A-tile node columns)
            *(unsigned short*)(smc + R_CAH * 4 + r * 368 + (128 + f) * 2) = bfh(v);
            *(unsigned short*)(smc + R_CAL * 4 + r * 368 + (128 + f) * 2) = bfh(bflo(v));
        }
        // zero C A-tile pad cols 160..175 (B overwrites 160..164)
        for (int idx = tid; idx < 1024; idx += NT) {
            int sp = idx >> 9, j = idx & 511, r = j >> 3, o = (j & 7) * 4;
            *(u32t*)(smc + (sp ? R_CAL : R_CAH) * 4 + r * 368 + 320 + o) = 0;
        }
    }
    __syncthreads();

    // ---------------- Phase B: an = adj_e @ node -> C A-tile bf16 ; rs, const cols --------
    // adjacency reconstructed from bf16 hi+lo (exact)
    {
        const int e = wid >> 2, fs = wid & 3, f0 = fs * 8;
        u64t acc[2][4];
        #pragma unroll
        for (int mh = 0; mh < 2; mh++)
            #pragma unroll
            for (int j = 0; j < 4; j++) acc[mh][j] = 0ull;
        float rs0 = 0.f, rs1 = 0.f;
        const char* ah0 = smc + R_AB_H * 4 + lane * 528 + e * 128;
        const char* al0 = smc + R_AB_L * 4 + lane * 528 + e * 128;
        const char* ah1 = ah0 + 32 * 528;
        const char* al1 = al0 + 32 * 528;
        const float* np = &smem[R_NODE + f0];
        #pragma unroll 2
        for (int n = 0; n < NN; n += 2) {
            float2 h0 = __bfloat1622float2(*(const __nv_bfloat162*)(ah0 + n * 2));
            float2 l0 = __bfloat1622float2(*(const __nv_bfloat162*)(al0 + n * 2));
            float2 h1 = __bfloat1622float2(*(const __nv_bfloat162*)(ah1 + n * 2));
            float2 l1 = __bfloat1622float2(*(const __nv_bfloat162*)(al1 + n * 2));
            float a00 = h0.x + l0.x, a01 = h0.y + l0.y;
            float a10 = h1.x + l1.x, a11 = h1.y + l1.y;
            rs0 += a00 + a01; rs1 += a10 + a11;
            {
                u64t s0 = splat2(a00), s1 = splat2(a10);
                ulonglong2 v0 = *(const ulonglong2*)(np + n * NODE_PITCH);
                ulonglong2 v1 = *(const ulonglong2*)(np + n * NODE_PITCH + 4);
                acc[0][0] = ffma2(acc[0][0], v0.x, s0); acc[0][1] = ffma2(acc[0][1], v0.y, s0);
                acc[0][2] = ffma2(acc[0][2], v1.x, s0); acc[0][3] = ffma2(acc[0][3], v1.y, s0);
                acc[1][0] = ffma2(acc[1][0], v0.x, s1); acc[1][1] = ffma2(acc[1][1], v0.y, s1);
                acc[1][2] = ffma2(acc[1][2], v1.x, s1); acc[1][3] = ffma2(acc[1][3], v1.y, s1);
            }
            {
                u64t s0 = splat2(a01), s1 = splat2(a11);
                ulonglong2 v0 = *(const ulonglong2*)(np + (n + 1) * NODE_PITCH);
                ulonglong2 v1 = *(const ulonglong2*)(np + (n + 1) * NODE_PITCH + 4);
                acc[0][0] = ffma2(acc[0][0], v0.x, s0); acc[0][1] = ffma2(acc[0][1], v0.y, s0);
                acc[0][2] = ffma2(acc[0][2], v1.x, s0); acc[0][3] = ffma2(acc[0][3], v1.y, s0);
                acc[1][0] = ffma2(acc[1][0], v0.x, s1); acc[1][1] = ffma2(acc[1][1], v0.y, s1);
                acc[1][2] = ffma2(acc[1][2], v1.x, s1); acc[1][3] = ffma2(acc[1][3], v1.y, s1);
            }
        }
        #pragma unroll
        for (int mh = 0; mh < 2; mh++) {
            int m = lane + mh * 32;
            float a[8];
            float2 x0 = unpack2(acc[mh][0]), x1 = unpack2(acc[mh][1]);
            float2 x2 = unpack2(acc[mh][2]), x3 = unpack2(acc[mh][3]);
            a[0] = x0.x; a[1] = x0.y; a[2] = x1.x; a[3] = x1.y;
            a[4] = x2.x; a[5] = x2.y; a[6] = x3.x; a[7] = x3.y;
            #pragma unroll
            for (int p = 0; p < 4; p++) {
                int k = e * 32 + f0 + 2 * p;
                *(u32t*)(smc + R_CAH * 4 + m * 368 + k * 2) = bfpair(a[2 * p], a[2 * p + 1]);
                *(u32t*)(smc + R_CAL * 4 + m * 368 + k * 2) =
                    bfpair(bflo(a[2 * p]), bflo(a[2 * p + 1]));
            }
        }
        if (fs == 0) {
            #pragma unroll
            for (int mh = 0; mh < 2; mh++) {
                int m = lane + mh * 32;
                float rs = mh ? rs1 : rs0;
                *(unsigned short*)(smc + R_CAH * 4 + m * 368 + (160 + e) * 2) = bfh(rs);
                *(unsigned short*)(smc + R_CAL * 4 + m * 368 + (160 + e) * 2) = bfh(bflo(rs));
                if (e == 0) {
                    *(unsigned short*)(smc + R_CAH * 4 + m * 368 + 164 * 2) = 0x3F80;
                    *(unsigned short*)(smc + R_CAL * 4 + m * 368 + 164 * 2) = 0;
                }
            }
        }
    }
    __syncthreads();

    // ---------------- Phase C: h1 via mma.sync (11 chunks) -> h1 into C A-tile in place ---
    {
        const int mb = wid & 3, m0 = mb * 16;
        const int us = wid >> 2, u0 = us * 32;
        float acc[4][4];
        #pragma unroll
        for (int j = 0; j < 4; j++) { acc[j][0] = acc[j][1] = acc[j][2] = acc[j][3] = 0.f; }
        const int al_r = (lane & 7) + ((lane >> 3) & 1) * 8;
        const int al_c8 = (lane >> 4) * 8;
        const u32t aHi = smb + R_CAH * 4 + (m0 + al_r) * 368;
        const u32t aLo = smb + R_CAL * 4 + (m0 + al_r) * 368;
        const int b_r = (lane & 7) + ((lane >> 4) << 3);
        const int b_k16 = ((lane >> 3) & 1) * 16;
        const int s_sp = tid >> 8, s_row = (tid & 255) >> 1, s_c8 = (tid & 1) * 8;
        const char* s_src = (const char*)g_W1pack + (size_t)(s_sp * 128 + s_row) * 352 + s_c8 * 2;
        char* s_dst = smc + R_WCH * 4 + s_sp * 6144 + s_row * 48 + s_c8 * 2;
        uint4 pf = *(const uint4*)(s_src);
        #pragma unroll 1
        for (int ck = 0; ck < 11; ck++) {
            *(uint4*)s_dst = pf;
            __syncthreads();
            if (ck < 10) pf = *(const uint4*)(s_src + (ck + 1) * 32);
            const int k0 = ck * 16;
            u32t ah0, ah1, ah2, ah3, al0, al1, al2, al3;
            LDSM_X4(ah0, ah1, ah2, ah3, aHi + (k0 + al_c8) * 2);
            LDSM_X4(al0, al1, al2, al3, aLo + (k0 + al_c8) * 2);
            #pragma unroll
            for (int t = 0; t < 2; t++) {
                u32t b0, b1, b2r, b3;
                LDSM_X4(b0, b1, b2r, b3,
                        smb + R_WCH * 4 + (u0 + t * 16 + b_r) * 48 + b_k16);
                MMA_BF16(acc[2 * t],     ah0, ah1, ah2, ah3, b0, b1);
                MMA_BF16(acc[2 * t + 1], ah0, ah1, ah2, ah3, b2r, b3);
                MMA_BF16(acc[2 * t],     al0, al1, al2, al3, b0, b1);
                MMA_BF16(acc[2 * t + 1], al0, al1, al2, al3, b2r, b3);
            }
            #pragma unroll
            for (int t = 0; t < 2; t++) {
                u32t b0, b1, b2r, b3;
                LDSM_X4(b0, b1, b2r, b3,
                        smb + R_WCH * 4 + 6144 + (u0 + t * 16 + b_r) * 48 + b_k16);
                MMA_BF16(acc[2 * t],     ah0, ah1, ah2, ah3, b0, b1);
                MMA_BF16(acc[2 * t + 1], ah0, ah1, ah2, ah3, b2r, b3);
            }
            __syncthreads();
        }
        // epilogue: h1 = tanh -> overwrite C A-tile cols 0..127 (an is dead; reads done)
        const int q = lane & 3, rw = lane >> 2;
        #pragma unroll
        for (int j = 0; j < 4; j++) {
            int u = u0 + 8 * j + 2 * q;
            #pragma unroll
            for (int h = 0; h < 2; h++) {
                int m = m0 + rw + 8 * h;
                float t0 = tanhf(acc[j][2 * h]), t1 = tanhf(acc[j][2 * h + 1]);
                *(u32t*)(smc + R_CAH * 4 + m * 368 + u * 2) = bfpair(t0, t1);
                *(u32t*)(smc + R_CAL * 4 + m * 368 + u * 2) = bfpair(bflo(t0), bflo(t1));
            }
        }
    }
    __syncthreads();

    // ---------------- Phase D: pre2 via mma.sync (10 chunks); epilogue -> pre2T bf16 ------
    {
        const int e = wid >> 2, nb = wid & 3, n0 = nb * 16;
        float acc[8][4];
        #pragma unroll
        for (int j = 0; j < 8; j++) { acc[j][0] = acc[j][1] = acc[j][2] = acc[j][3] = 0.f; }
        const int al_r = (lane & 7) + ((lane >> 3) & 1) * 8;
        const int al_c8 = (lane >> 4) * 8;
        const u32t aHi = smb + R_CAH * 4 + (n0 + al_r) * 368;
        const u32t aLo = smb + R_CAL * 4 + (n0 + al_r) * 368;
        const int b_r = (lane & 7) + ((lane >> 4) << 3);
        const int b_k16 = ((lane >> 3) & 1) * 16;
        const int i0 = tid, i1 = tid + 512;
        const int sp0 = i0 >> 9, j0 = i0 & 511, row0 = j0 >> 1, c80 = (j0 & 1) * 8;
        const int sp1 = i1 >> 9, j1 = i1 & 511, row1 = j1 >> 1, c81 = (j1 & 1) * 8;
        const char* src0 = (const char*)g_W2pack + (size_t)(sp0 * 256 + row0) * 320 + c80 * 2;
        const char* src1 = (const char*)g_W2pack + (size_t)(sp1 * 256 + row1) * 320 + c81 * 2;
        char* dst0 = smc + R_WCH * 4 + sp0 * 12288 + row0 * 48 + c80 * 2;
        char* dst1 = smc + R_WCH * 4 + sp1 * 12288 + row1 * 48 + c81 * 2;
        uint4 pf0 = *(const uint4*)(src0);
        uint4 pf1 = *(const uint4*)(src1);
        #pragma unroll 1
        for (int ck = 0; ck < 10; ck++) {
            *(uint4*)dst0 = pf0;
            *(uint4*)dst1 = pf1;
            __syncthreads();
            if (ck < 9) {
                pf0 = *(const uint4*)(src0 + (ck + 1) * 32);
                pf1 = *(const uint4*)(src1 + (ck + 1) * 32);
            }
            const int k0 = ck * 16;
            u32t ah0, ah1, ah2, ah3, al0, al1, al2, al3;
            LDSM_X4(ah0, ah1, ah2, ah3, aHi + (k0 + al_c8) * 2);
            LDSM_X4(al0, al1, al2, al3, aLo + (k0 + al_c8) * 2);
            #pragma unroll
            for (int t = 0; t < 4; t++) {
                u32t b0, b1, b2r, b3;
                LDSM_X4(b0, b1, b2r, b3,
                        smb + R_WCH * 4 + (e * 64 + t * 16 + b_r) * 48 + b_k16);
                MMA_BF16(acc[2 * t],     ah0, ah1, ah2, ah3, b0, b1);
                MMA_BF16(acc[2 * t + 1], ah0, ah1, ah2, ah3, b2r, b3);
                MMA_BF16(acc[2 * t],     al0, al1, al2, al3, b0, b1);
                MMA_BF16(acc[2 * t + 1], al0, al1, al2, al3, b2r, b3);
            }
            #pragma unroll
            for (int t = 0; t < 4; t++) {
                u32t b0, b1, b2r, b3;
                LDSM_X4(b0, b1, b2r, b3,
                        smb + R_WCH * 4 + 12288 + (e * 64 + t * 16 + b_r) * 48 + b_k16);
                MMA_BF16(acc[2 * t],     ah0, ah1, ah2, ah3, b0, b1);
                MMA_BF16(acc[2 * t + 1], ah0, ah1, ah2, ah3, b2r, b3);
            }
            __syncthreads();
        }
        // epilogue: pre2T[u][n'] = bf16 hi/lo of (acc + b2[e][u]) ; overwrites dead WCH
        const int q = lane & 3, rw = lane >> 2;
        char* pH = smc + R_PTH * 4;
        char* pL = smc + R_PTL * 4;
        const int np0 = e * 64 + n0 + rw;
        #pragma unroll
        for (int j = 0; j < 8; j++) {
            int u = 8 * j + 2 * q;
            float2 bb = *(const float2*)(b2 + e * 64 + u);
            float v00 = acc[j][0] + bb.x, v01 = acc[j][1] + bb.y;
            float v10 = acc[j][2] + bb.x, v11 = acc[j][3] + bb.y;
            *(unsigned short*)(pH + u * 528 + np0 * 2)           = bfh(v00);
            *(unsigned short*)(pL + u * 528 + np0 * 2)           = bfh(bflo(v00));
            *(unsigned short*)(pH + (u + 1) * 528 + np0 * 2)     = bfh(v01);
            *(unsigned short*)(pL + (u + 1) * 528 + np0 * 2)     = bfh(bflo(v01));
            *(unsigned short*)(pH + u * 528 + (np0 + 8) * 2)     = bfh(v10);
            *(unsigned short*)(pL + u * 528 + (np0 + 8) * 2)     = bfh(bflo(v10));
            *(unsigned short*)(pH + (u + 1) * 528 + (np0 + 8) * 2) = bfh(v11);
            *(unsigned short*)(pL + (u + 1) * 528 + (np0 + 8) * 2) = bfh(bflo(v11));
        }
    }
    __syncthreads();

    // ---------------- Phase E: h2 via ONE mma.sync GEMM, K=256, no barriers ---------------
    {
        const int mb = wid & 3, m0 = mb * 16;
        const int ub = wid >> 2, u0 = ub * 16;
        float acc[2][4];
        acc[0][0] = acc[0][1] = acc[0][2] = acc[0][3] = 0.f;
        acc[1][0] = acc[1][1] = acc[1][2] = acc[1][3] = 0.f;
        const int al_r = (lane & 7) + ((lane >> 3) & 1) * 8;
        const int al_c8 = (lane >> 4) * 8;
        const u32t aHi = smb + R_AB_H * 4 + (m0 + al_r) * 528;
        const u32t aLo = smb + R_AB_L * 4 + (m0 + al_r) * 528;
        const int b_r = (lane & 7) + ((lane >> 4) << 3);
        const int b_k16 = ((lane >> 3) & 1) * 16;
        const u32t bHi = smb + R_PTH * 4 + (u0 + b_r) * 528 + b_k16;
        const u32t bLo = smb + R_PTL * 4 + (u0 + b_r) * 528 + b_k16;
        #pragma unroll 2
        for (int ck = 0; ck < 16; ck++) {
            const int k0 = ck * 16;
            u32t ah0, ah1, ah2, ah3, al0, al1, al2, al3;
            LDSM_X4(ah0, ah1, ah2, ah3, aHi + (k0 + al_c8) * 2);
            LDSM_X4(al0, al1, al2, al3, aLo + (k0 + al_c8) * 2);
            u32t bh0, bh1, bh2, bh3, bl0, bl1, bl2, bl3;
            LDSM_X4(bh0, bh1, bh2, bh3, bHi + k0 * 2);
            LDSM_X4(bl0, bl1, bl2, bl3, bLo + k0 * 2);
            MMA_BF16(acc[0], ah0, ah1, ah2, ah3, bh0, bh1);
            MMA_BF16(acc[1], ah0, ah1, ah2, ah3, bh2, bh3);
            MMA_BF16(acc[0], ah0, ah1, ah2, ah3, bl0, bl1);
            MMA_BF16(acc[1], ah0, ah1, ah2, ah3, bl2, bl3);
            MMA_BF16(acc[0], al0, al1, al2, al3, bh0, bh1);
            MMA_BF16(acc[1], al0, al1, al2, al3, bh2, bh3);
        }
        // epilogue: + node@V2 + c2 (fp32), tanh -> F act tiles [m][u]
        const int q = lane & 3, rw = lane >> 2;
        float nv[2][4];
        nv[0][0] = nv[0][1] = nv[0][2] = nv[0][3] = 0.f;
        nv[1][0] = nv[1][1] = nv[1][2] = nv[1][3] = 0.f;
        const float* nr0 = &smem[R_NODE + (m0 + rw) * NODE_PITCH];
        const float* nr1 = nr0 + 8 * NODE_PITCH;
        #pragma unroll 4
        for (int f = 0; f < FF; f++) {
            float n0v = nr0[f], n1v = nr1[f];
            float2 va = *(const float2*)(V2 + f * 64 + u0 + 2 * q);
            float2 vb = *(const float2*)(V2 + f * 64 + u0 + 8 + 2 * q);
            nv[0][0] += n0v * va.x; nv[0][1] += n0v * va.y;
            nv[0][2] += n0v * vb.x; nv[0][3] += n0v * vb.y;
            nv[1][0] += n1v * va.x; nv[1][1] += n1v * va.y;
            nv[1][2] += n1v * vb.x; nv[1][3] += n1v * vb.y;
        }
        float2 ca = *(const float2*)(c2 + u0 + 2 * q);
        float2 cb = *(const float2*)(c2 + u0 + 8 + 2 * q);
        #pragma unroll
        for (int mh = 0; mh < 2; mh++) {
            int m = m0 + rw + mh * 8;
            #pragma unroll
            for (int t = 0; t < 2; t++) {
                int u = u0 + t * 8 + 2 * q;
                float x0 = acc[t][2 * mh]     + nv[mh][2 * t]     + (t ? cb.x : ca.x);
                float x1 = acc[t][2 * mh + 1] + nv[mh][2 * t + 1] + (t ? cb.y : ca.y);
                float t0 = tanhf(x0), t1 = tanhf(x1);
                *(u32t*)(smc + R_FAH * 4 + m * 224 + u * 2) = bfpair(t0, t1);
                *(u32t*)(smc + R_FAL * 4 + m * 224 + u * 2) = bfpair(bflo(t0), bflo(t1));
            }
        }
        // F act tile cols 64..95 = node
        for (int idx = tid; idx < NN * 32; idx += NT) {
            int r = idx >> 5, k = 64 + (idx & 31);
            float v = smem[R_NODE + r * NODE_PITCH + (k - 64)];
            *(unsigned short*)(smc + R_FAH * 4 + r * 224 + k * 2) = bfh(v);
            *(unsigned short*)(smc + R_FAL * 4 + r * 224 + k * 2) = bfh(bflo(v));
        }
    }
    __syncthreads();

    // ---------------- Phase F: gate pre-acts via mma.sync (6 chunks, prefetched) ----------
    {
        const int uq = wid >> 2, nb = wid & 3, n0 = nb * 16;
        float acc[8][4];
        #pragma unroll
        for (int j = 0; j < 8; j++) { acc[j][0] = acc[j][1] = acc[j][2] = acc[j][3] = 0.f; }
        const int al_r = (lane & 7) + ((lane >> 3) & 1) * 8;
        const int al_c8 = (lane >> 4) * 8;
        const u32t aHi = smb + R_FAH * 4 + (n0 + al_r) * 224;
        const u32t aLo = smb + R_FAL * 4 + (n0 + al_r) * 224;
        const int b_r = (lane & 7) + ((lane >> 4) << 3);
        const int b_k16 = ((lane >> 3) & 1) * 16;
        const int i0 = tid, i1 = tid + 512;
        const int sp0 = i0 >> 9, j0 = i0 & 511, row0 = j0 >> 1, c80 = (j0 & 1) * 8;
        const int sp1 = i1 >> 9, j1 = i1 & 511, row1 = j1 >> 1, c81 = (j1 & 1) * 8;
        const char* src0 = (const char*)g_WGpack + (size_t)(sp0 * 256 + row0) * 192 + c80 * 2;
        const char* src1 = (const char*)g_WGpack + (size_t)(sp1 * 256 + row1) * 192 + c81 * 2;
        char* dst0 = smc + R_WCH * 4 + sp0 * 12288 + row0 * 48 + c80 * 2;
        char* dst1 = smc + R_WCH * 4 + sp1 * 12288 + row1 * 48 + c81 * 2;
        uint4 pf0 = *(const uint4*)(src0);
        uint4 pf1 = *(const uint4*)(src1);
        #pragma unroll 1
        for (int ck = 0; ck < 6; ck++) {
            *(uint4*)dst0 = pf0;
            *(uint4*)dst1 = pf1;
            __syncthreads();
            if (ck < 5) {
                pf0 = *(const uint4*)(src0 + (ck + 1) * 32);
                pf1 = *(const uint4*)(src1 + (ck + 1) * 32);
            }
            const int k0 = ck * 16;
            u32t ah0, ah1, ah2, ah3, al0, al1, al2, al3;
            LDSM_X4(ah0, ah1, ah2, ah3, aHi + (k0 + al_c8) * 2);
            LDSM_X4(al0, al1, al2, al3, aLo + (k0 + al_c8) * 2);
            #pragma unroll
            for (int t = 0; t < 4; t++) {
                u32t b0, b1, b2r, b3;
                LDSM_X4(b0, b1, b2r, b3,
                        smb + R_WCH * 4 + (uq * 64 + t * 16 + b_r) * 48 + b_k16);
                MMA_BF16(acc[2 * t],     ah0, ah1, ah2, ah3, b0, b1);
                MMA_BF16(acc[2 * t + 1], ah0, ah1, ah2, ah3, b2r, b3);
                MMA_BF16(acc[2 * t],     al0, al1, al2, al3, b0, b1);
                MMA_BF16(acc[2 * t + 1], al0, al1, al2, al3, b2r, b3);
            }
            #pragma unroll
            for (int t = 0; t < 4; t++) {
                u32t b0, b1, b2r, b3;
                LDSM_X4(b0, b1, b2r, b3,
                        smb + R_WCH * 4 + 12288 + (uq * 64 + t * 16 + b_r) * 48 + b_k16);
                MMA_BF16(acc[2 * t],     ah0, ah1, ah2, ah3, b0, b1);
                MMA_BF16(acc[2 * t + 1], ah0, ah1, ah2, ah3, b2r, b3);
            }
            __syncthreads();
        }
        // epilogue: pi/pj (+bias) over dead AB region
        const int q = lane & 3, rw = lane >> 2;
        #pragma unroll
        for (int j = 0; j < 8; j++) {
            int up = uq * 64 + 8 * j + 2 * q;
            int mat = up >> 7, uu = up & 127;
            float2 bb = *(const float2*)((mat ? bj : bi) + uu);
            int base = (mat ? R_PJ : R_PI) + (n0 + rw) * PI_PITCH + uu;
            smem[base]                    = acc[j][0] + bb.x;
            smem[base + 1]                = acc[j][1] + bb.y;
            smem[base + 8 * PI_PITCH]     = acc[j][2] + bb.x;
            smem[base + 8 * PI_PITCH + 1] = acc[j][3] + bb.y;
        }
    }
    __syncthreads();

    // ---------------- Phase G: out[b][u] = tanh(sum_n sigmoid(pi)*tanh(pj)) ----------------
    {
        const int qg = tid >> 7, u = tid & 127;
        float s = 0.0f;
        #pragma unroll
        for (int i = 0; i < 16; i++) {
            int n = qg * 16 + i;
            float pi = smem[R_PI + n * PI_PITCH + u];
            float pj = smem[R_PJ + n * PI_PITCH + u];
            s += sigmoidf_(pi) * tanhf(pj);
        }
        smem[R_RED + qg * UAC + u] = s;
    }
    __syncthreads();
    if (tid < UAC) {
        float s = smem[R_RED + tid] + smem[R_RED + UAC + tid]
                + smem[R_RED + 2 * UAC + tid] + smem[R_RED + 3 * UAC + tid];
        out[(size_t)b * UAC + tid] = tanhf(s);
    }
}

extern "C" void kernel_launch(void* const* d_in, const int* in_sizes, int n_in,
                              void* d_out, int out_size) {
    (void)in_sizes; (void)n_in; (void)out_size;
    const float* adjacency = (const float*)d_in[0];
    const float* node = (const float*)d_in[2];
    const float* W1 = (const float*)d_in[3];
    const float* b1 = (const float*)d_in[4];
    const float* V1 = (const float*)d_in[5];
    const float* c1 = (const float*)d_in[6];
    const float* W2 = (const float*)d_in[7];
    const float* b2 = (const float*)d_in[8];
    const float* V2 = (const float*)d_in[9];
    const float* c2 = (const float*)d_in[10];
    const float* Wi = (const float*)d_in[11];
    const float* bi = (const float*)d_in[12];
    const float* Wj = (const float*)d_in[13];
    const float* bj = (const float*)d_in[14];

    preconv_kernel<<<344, 256>>>(W2, Wi, Wj, W1, V1, b1, c1);
    cudaFuncSetAttribute(encoder_kernel,
                         cudaFuncAttributeMaxDynamicSharedMemorySize, SMEM_BYTES);
    encoder_kernel<<<BATCH, NT, SMEM_BYTES>>>(adjacency, node,
                                              b2, V2, c2,
                                              bi, bj,
                                              (float*)d_out);
}

// round 15
// speedup vs baseline: 2.0270x; 1.0348x over previous
#include <cuda_runtime.h>
#include <cuda_bf16.h>
#include <math.h>
#include <cstdint>

typedef unsigned long long u64t;
typedef unsigned int u32t;

#define EM1 4
#define NN 64
#define FF 32
#define U1C 128
#define U2C 64
#define UAC 128
#define NT 512
#define BATCH 2048

#define NODE_PITCH 36
#define PI_PITCH 132
#define ABP 624          // byte pitch of AB / PT tiles (304 cols bf16 + pad, odd x16B)

// ---- smem regions (float indices) ----
#define R_AB_H 0         // adj+node+1 A-tile hi bf16 [64m][ABP] = 9984 fl (A..E); then pi/pj
#define R_AB_L 9984      // -> 19968
#define R_PI   0         // pi [64][132] (F-epi..G)
#define R_PJ   8448      // pj
#define R_NODE 19968     // node fp32 [64][36] = 2304 -> 22272
#define R_RED  22272     // 512 -> 22784
#define R_CAH  22784     // C A-tile hi bf16 [64][368B] = 5888 fl (B..D; h1 written in place)
#define R_CAL  28672     // -> 34560
#define R_FAH  22784     // F act hi [64][224B] = 3584 (E..F, aliases dead CA)
#define R_FAL  26368     // -> 29952
#define R_PTH  34560     // pre2T hi bf16 [64u][ABP] = 9984 fl (D-epi..E)
#define R_PTL  44544     // -> 54528
#define R_NT_H 34560     // nodeT hi bf16 [48f][144B] = 1728 fl (A..B, aliases PT)
#define R_NT_L 36288     // -> 38016
#define R_WCH  34560     // weight chunks (C:12KB, D/F:24KB), aliases PT (timeline-disjoint)
#define SMEM_FLOATS 54528
#define SMEM_BYTES (SMEM_FLOATS*4)   // 218112 B

// packed bf16 weights [split][row=u][k]
__device__ __align__(16) __nv_bfloat16 g_W2pack[2][256][160];  // D: row=e*64+u
__device__ __align__(16) __nv_bfloat16 g_WGpack[2][256][96];   // F: row=mat*128+u
__device__ __align__(16) __nv_bfloat16 g_W1pack[2][128][176];  // C: row=u, k=[W1|V1|b1|c1|0]

__device__ __forceinline__ float sigmoid_fast(float x) {
    return __fdividef(1.0f, 1.0f + __expf(-x));
}
__device__ __forceinline__ float tanh_fast(float x) {
    return 1.0f - __fdividef(2.0f, __expf(2.0f * x) + 1.0f);
}

// ---- bf16 helpers ----
__device__ __forceinline__ u32t bfpair(float a, float b) {
    u32t lo = (u32t)__bfloat16_as_ushort(__float2bfloat16_rn(a));
    u32t hi = (u32t)__bfloat16_as_ushort(__float2bfloat16_rn(b));
    return lo | (hi << 16);
}
__device__ __forceinline__ float bflo(float x) { return x - __bfloat162float(__float2bfloat16_rn(x)); }
__device__ __forceinline__ unsigned short bfh(float x) {
    return __bfloat16_as_ushort(__float2bfloat16_rn(x));
}
__device__ __forceinline__ u32t smem_u32(const void* p) {
    u32t a; asm("{ .reg .u64 t; cvta.to.shared.u64 t, %1; cvt.u32.u64 %0, t; }" : "=r"(a) : "l"(p));
    return a;
}

#define LDSM_X4(r0, r1, r2, r3, addr) \
    asm volatile("ldmatrix.sync.aligned.m8n8.x4.shared.b16 {%0,%1,%2,%3}, [%4];" \
                 : "=r"(r0), "=r"(r1), "=r"(r2), "=r"(r3) : "r"(addr))

#define MMA_BF16(c, a0, a1, a2, a3, b0, b1) \
    asm volatile("mma.sync.aligned.m16n8k16.row.col.f32.bf16.bf16.f32 " \
                 "{%0,%1,%2,%3}, {%4,%5,%6,%7}, {%8,%9}, {%0,%1,%2,%3};" \
                 : "+f"((c)[0]), "+f"((c)[1]), "+f"((c)[2]), "+f"((c)[3]) \
                 : "r"(a0), "r"(a1), "r"(a2), "r"(a3), "r"(b0), "r"(b1))

// ---- weight preconversion ----
__global__ void preconv_kernel(const float* __restrict__ W2,
                               const float* __restrict__ Wi,
                               const float* __restrict__ Wj,
                               const float* __restrict__ W1,
                               const float* __restrict__ V1,
                               const float* __restrict__ b1,
                               const float* __restrict__ c1) {
    int i = blockIdx.x * 256 + threadIdx.x;
    if (i < 256 * 160) {
        int row = i / 160, k = i % 160;
        int e = row >> 6, u = row & 63;
        float w = W2[(e * 160 + k) * 64 + u];
        __nv_bfloat16 h = __float2bfloat16_rn(w);
        g_W2pack[0][row][k] = h;
        g_W2pack[1][row][k] = __float2bfloat16_rn(w - __bfloat162float(h));
    } else if (i < 256 * 160 + 256 * 96) {
        int j = i - 256 * 160;
        int row = j / 96, k = j % 96;
        int mat = row >> 7, u = row & 127;
        float w = (mat ? Wj : Wi)[k * 128 + u];
        __nv_bfloat16 h = __float2bfloat16_rn(w);
        g_WGpack[0][row][k] = h;
        g_WGpack[1][row][k] = __float2bfloat16_rn(w - __bfloat162float(h));
    } else if (i < 256 * 160 + 256 * 96 + 128 * 176) {
        int j = i - (256 * 160 + 256 * 96);
        int u = j / 176, k = j % 176;
        float w;
        if (k < 128)      w = W1[k * 128 + u];
        else if (k < 160) w = V1[(k - 128) * 128 + u];
        else if (k < 164) w = b1[(k - 160) * 128 + u];
        else if (k == 164) w = c1[u];
        else              w = 0.0f;
        __nv_bfloat16 h = __float2bfloat16_rn(w);
        g_W1pack[0][u][k] = h;
        g_W1pack[1][u][k] = __float2bfloat16_rn(w - __bfloat162float(h));
    }
}

__global__ void __launch_bounds__(NT, 1)
encoder_kernel(const float* __restrict__ adjacency,
               const float* __restrict__ node,
               const float* __restrict__ b2, const float* __restrict__ V2,
               const float* __restrict__ c2,
               const float* __restrict__ bi, const float* __restrict__ bj,
               float* __restrict__ out)
{
    extern __shared__ float smem[];
    char* smc = (char*)smem;
    const int b = blockIdx.x;
    const int tid = threadIdx.x;
    const int wid = tid >> 5;
    const int lane = tid & 31;
    const u32t smb = smem_u32(smem);

    // ---------------- Phase A: stage all bf16 tiles ----------------------------------------
    {
        const float* adjB = adjacency + (size_t)b * (NN * NN * 5);
        for (int idx = tid; idx < NN * NN * 5; idx += NT) {
            float v = adjB[idx];
            int e = idx % 5;
            int r = idx / 5;
            if (e > 0) {
                int m = r >> 6, n = r & 63;
                int col = (e - 1) * 64 + n;
                *(unsigned short*)(smc + R_AB_H * 4 + m * ABP + col * 2) = bfh(v);
                *(unsigned short*)(smc + R_AB_L * 4 + m * ABP + col * 2) = bfh(bflo(v));
            }
        }
        const float* nodeB = node + (size_t)b * (NN * FF);
        for (int idx = tid; idx < NN * FF; idx += NT) {
            int r = idx >> 5, f = idx & 31;
            float v = nodeB[idx];
            smem[R_NODE + r * NODE_PITCH + f] = v;
            unsigned short h = bfh(v), l = bfh(bflo(v));
            // C A-tile cols 128..159
            *(unsigned short*)(smc + R_CAH * 4 + r * 368 + (128 + f) * 2) = h;
            *(unsigned short*)(smc + R_CAL * 4 + r * 368 + (128 + f) * 2) = l;
            // E A-tile cols 256..287 (node term of V2 fold)
            *(unsigned short*)(smc + R_AB_H * 4 + r * ABP + (256 + f) * 2) = h;
            *(unsigned short*)(smc + R_AB_L * 4 + r * ABP + (256 + f) * 2) = l;
            // nodeT for Phase B
            *(unsigned short*)(smc + R_NT_H * 4 + f * 144 + r * 2) = h;
            *(unsigned short*)(smc + R_NT_L * 4 + f * 144 + r * 2) = l;
        }
        // E A-tile cols 288..303: col 288 = 1 (hi), rest/lo = 0
        for (int idx = tid; idx < 2048; idx += NT) {
            int sp = idx >> 10, j = idx & 1023, r = j >> 4, c = 288 + (j & 15);
            unsigned short v = (sp == 0 && c == 288) ? (unsigned short)0x3F80 : (unsigned short)0;
            *(unsigned short*)(smc + (sp ? R_AB_L : R_AB_H) * 4 + r * ABP + c * 2) = v;
        }
        // C A-tile cols 164..175: col 164 = 1 (hi), rest/lo = 0
        for (int idx = tid; idx < 1536; idx += NT) {
            int sp = idx / 768, j = idx % 768, r = j / 12, c = 164 + j % 12;
            unsigned short v = (sp == 0 && c == 164) ? (unsigned short)0x3F80 : (unsigned short)0;
            *(unsigned short*)(smc + (sp ? R_CAL : R_CAH) * 4 + r * 368 + c * 2) = v;
        }
        // nodeT rows 32..47: row 32 = ones (hi), rest/lo = 0
        for (int idx = tid; idx < 2048; idx += NT) {
            int sp = idx >> 10, j = idx & 1023, f = 32 + (j >> 6), n = j & 63;
            unsigned short v = (sp == 0 && f == 32) ? (unsigned short)0x3F80 : (unsigned short)0;
            *(unsigned short*)(smc + (sp ? R_NT_L : R_NT_H) * 4 + f * 144 + n * 2) = v;
        }
    }
    __syncthreads();

    // ---------------- Phase B: an_e = adj_e @ nodeT^T via mma.sync (rowsum via ones row) ---
    {
        const int e = wid >> 2, mb = wid & 3, m0 = mb * 16;
        float acc[5][4];
        #pragma unroll
        for (int j = 0; j < 5; j++) { acc[j][0] = acc[j][1] = acc[j][2] = acc[j][3] = 0.f; }
        const int al_r = (lane & 7) + ((lane >> 3) & 1) * 8;
        const int al_c8 = (lane >> 4) * 8;
        const u32t aHi = smb + R_AB_H * 4 + (m0 + al_r) * ABP + e * 128;
        const u32t aLo = smb + R_AB_L * 4 + (m0 + al_r) * ABP + e * 128;
        const int b_r = (lane & 7) + ((lane >> 4) << 3);
        const int b_k16 = ((lane >> 3) & 1) * 16;
        const u32t ntH = smb + R_NT_H * 4 + b_r * 144 + b_k16;
        const u32t ntL = smb + R_NT_L * 4 + b_r * 144 + b_k16;
        #pragma unroll
        for (int ck = 0; ck < 4; ck++) {
            const int k0 = ck * 16;
            u32t ah0, ah1, ah2, ah3, al0, al1, al2, al3;
            LDSM_X4(ah0, ah1, ah2, ah3, aHi + (k0 + al_c8) * 2);
            LDSM_X4(al0, al1, al2, al3, aLo + (k0 + al_c8) * 2);
            #pragma unroll
            for (int t = 0; t < 3; t++) {
                u32t bh0, bh1, bh2, bh3, bl0, bl1, bl2, bl3;
                LDSM_X4(bh0, bh1, bh2, bh3, ntH + t * 2304 + k0 * 2);
                LDSM_X4(bl0, bl1, bl2, bl3, ntL + t * 2304 + k0 * 2);
                MMA_BF16(acc[2 * t], ah0, ah1, ah2, ah3, bh0, bh1);
                MMA_BF16(acc[2 * t], ah0, ah1, ah2, ah3, bl0, bl1);
                MMA_BF16(acc[2 * t], al0, al1, al2, al3, bh0, bh1);
                if (t < 2) {
                    MMA_BF16(acc[2 * t + 1], ah0, ah1, ah2, ah3, bh2, bh3);
                    MMA_BF16(acc[2 * t + 1], ah0, ah1, ah2, ah3, bl2, bl3);
                    MMA_BF16(acc[2 * t + 1], al0, al1, al2, al3, bh2, bh3);
                }
            }
        }
        // epilogue: an (cols f = nb*8+2q) -> C A-tile col e*32+f ; rowsum (col 32) -> col 160+e
        const int q = lane & 3, rw = lane >> 2;
        #pragma unroll
        for (int nb = 0; nb < 4; nb++) {
            int k = e * 32 + nb * 8 + 2 * q;
            int m = m0 + rw;
            *(u32t*)(smc + R_CAH * 4 + m * 368 + k * 2) = bfpair(acc[nb][0], acc[nb][1]);
            *(u32t*)(smc + R_CAL * 4 + m * 368 + k * 2) =
                bfpair(bflo(acc[nb][0]), bflo(acc[nb][1]));
            *(u32t*)(smc + R_CAH * 4 + (m + 8) * 368 + k * 2) = bfpair(acc[nb][2], acc[nb][3]);
            *(u32t*)(smc + R_CAL * 4 + (m + 8) * 368 + k * 2) =
                bfpair(bflo(acc[nb][2]), bflo(acc[nb][3]));
        }
        if (q == 0) {
            int c = (160 + e) * 2;
            int m = m0 + rw;
            *(unsigned short*)(smc + R_CAH * 4 + m * 368 + c) = bfh(acc[4][0]);
            *(unsigned short*)(smc + R_CAL * 4 + m * 368 + c) = bfh(bflo(acc[4][0]));
            *(unsigned short*)(smc + R_CAH * 4 + (m + 8) * 368 + c) = bfh(acc[4][2]);
            *(unsigned short*)(smc + R_CAL * 4 + (m + 8) * 368 + c) = bfh(bflo(acc[4][2]));
        }
    }
    __syncthreads();

    // ---------------- Phase C: h1 via mma.sync (11 chunks) -> h1 into C A-tile in place ---
    {
        const int mb = wid & 3, m0 = mb * 16;
        const int us = wid >> 2, u0 = us * 32;
        float acc[4][4];
        #pragma unroll
        for (int j = 0; j < 4; j++) { acc[j][0] = acc[j][1] = acc[j][2] = acc[j][3] = 0.f; }
        const int al_r = (lane & 7) + ((lane >> 3) & 1) * 8;
        const int al_c8 = (lane >> 4) * 8;
        const u32t aHi = smb + R_CAH * 4 + (m0 + al_r) * 368;
        const u32t aLo = smb + R_CAL * 4 + (m0 + al_r) * 368;
        const int b_r = (lane & 7) + ((lane >> 4) << 3);
        const int b_k16 = ((lane >> 3) & 1) * 16;
        const int s_sp = tid >> 8, s_row = (tid & 255) >> 1, s_c8 = (tid & 1) * 8;
        const char* s_src = (const char*)g_W1pack + (size_t)(s_sp * 128 + s_row) * 352 + s_c8 * 2;
        char* s_dst = smc + R_WCH * 4 + s_sp * 6144 + s_row * 48 + s_c8 * 2;
        uint4 pf = *(const uint4*)(s_src);
        #pragma unroll 1
        for (int ck = 0; ck < 11; ck++) {
            *(uint4*)s_dst = pf;
            __syncthreads();
            if (ck < 10) pf = *(const uint4*)(s_src + (ck + 1) * 32);
            const int k0 = ck * 16;
            u32t ah0, ah1, ah2, ah3, al0, al1, al2, al3;
            LDSM_X4(ah0, ah1, ah2, ah3, aHi + (k0 + al_c8) * 2);
            LDSM_X4(al0, al1, al2, al3, aLo + (k0 + al_c8) * 2);
            #pragma unroll
            for (int t = 0; t < 2; t++) {
                u32t b0, b1, b2r, b3;
                LDSM_X4(b0, b1, b2r, b3,
                        smb + R_WCH * 4 + (u0 + t * 16 + b_r) * 48 + b_k16);
                MMA_BF16(acc[2 * t],     ah0, ah1, ah2, ah3, b0, b1);
                MMA_BF16(acc[2 * t + 1], ah0, ah1, ah2, ah3, b2r, b3);
                MMA_BF16(acc[2 * t],     al0, al1, al2, al3, b0, b1);
                MMA_BF16(acc[2 * t + 1], al0, al1, al2, al3, b2r, b3);
            }
            #pragma unroll
            for (int t = 0; t < 2; t++) {
                u32t b0, b1, b2r, b3;
                LDSM_X4(b0, b1, b2r, b3,
                        smb + R_WCH * 4 + 6144 + (u0 + t * 16 + b_r) * 48 + b_k16);
                MMA_BF16(acc[2 * t],     ah0, ah1, ah2, ah3, b0, b1);
                MMA_BF16(acc[2 * t + 1], ah0, ah1, ah2, ah3, b2r, b3);
            }
            __syncthreads();
        }
        // epilogue: h1 = tanh -> overwrite C A-tile cols 0..127
        const int q = lane & 3, rw = lane >> 2;
        #pragma unroll
        for (int j = 0; j < 4; j++) {
            int u = u0 + 8 * j + 2 * q;
            #pragma unroll
            for (int h = 0; h < 2; h++) {
                int m = m0 + rw + 8 * h;
                float t0 = tanh_fast(acc[j][2 * h]), t1 = tanh_fast(acc[j][2 * h + 1]);
                *(u32t*)(smc + R_CAH * 4 + m * 368 + u * 2) = bfpair(t0, t1);
                *(u32t*)(smc + R_CAL * 4 + m * 368 + u * 2) = bfpair(bflo(t0), bflo(t1));
            }
        }
    }
    __syncthreads();

    // ---------------- Phase D: pre2 via mma.sync (10 chunks); epilogue -> pre2T(+V2,c2) ----
    {
        const int e = wid >> 2, nb = wid & 3, n0 = nb * 16;
        float acc[8][4];
        #pragma unroll
        for (int j = 0; j < 8; j++) { acc[j][0] = acc[j][1] = acc[j][2] = acc[j][3] = 0.f; }
        const int al_r = (lane & 7) + ((lane >> 3) & 1) * 8;
        const int al_c8 = (lane >> 4) * 8;
        const u32t aHi = smb + R_CAH * 4 + (n0 + al_r) * 368;
        const u32t aLo = smb + R_CAL * 4 + (n0 + al_r) * 368;
        const int b_r = (lane & 7) + ((lane >> 4) << 3);
        const int b_k16 = ((lane >> 3) & 1) * 16;
        const int i0 = tid, i1 = tid + 512;
        const int sp0 = i0 >> 9, j0 = i0 & 511, row0 = j0 >> 1, c80 = (j0 & 1) * 8;
        const int sp1 = i1 >> 9, j1 = i1 & 511, row1 = j1 >> 1, c81 = (j1 & 1) * 8;
        const char* src0 = (const char*)g_W2pack + (size_t)(sp0 * 256 + row0) * 320 + c80 * 2;
        const char* src1 = (const char*)g_W2pack + (size_t)(sp1 * 256 + row1) * 320 + c81 * 2;
        char* dst0 = smc + R_WCH * 4 + sp0 * 12288 + row0 * 48 + c80 * 2;
        char* dst1 = smc + R_WCH * 4 + sp1 * 12288 + row1 * 48 + c81 * 2;
        uint4 pf0 = *(const uint4*)(src0);
        uint4 pf1 = *(const uint4*)(src1);
        #pragma unroll 1
        for (int ck = 0; ck < 10; ck++) {
            *(uint4*)dst0 = pf0;
            *(uint4*)dst1 = pf1;
            __syncthreads();
            if (ck < 9) {
                pf0 = *(const uint4*)(src0 + (ck + 1) * 32);
                pf1 = *(const uint4*)(src1 + (ck + 1) * 32);
            }
            const int k0 = ck * 16;
            u32t ah0, ah1, ah2, ah3, al0, al1, al2, al3;
            LDSM_X4(ah0, ah1, ah2, ah3, aHi + (k0 + al_c8) * 2);
            LDSM_X4(al0, al1, al2, al3, aLo + (k0 + al_c8) * 2);
            #pragma unroll
            for (int t = 0; t < 4; t++) {
                u32t b0, b1, b2r, b3;
                LDSM_X4(b0, b1, b2r, b3,
                        smb + R_WCH * 4 + (e * 64 + t * 16 + b_r) * 48 + b_k16);
                MMA_BF16(acc[2 * t],     ah0, ah1, ah2, ah3, b0, b1);
                MMA_BF16(acc[2 * t + 1], ah0, ah1, ah2, ah3, b2r, b3);
                MMA_BF16(acc[2 * t],     al0, al1, al2, al3, b0, b1);
                MMA_BF16(acc[2 * t + 1], al0, al1, al2, al3, b2r, b3);
            }
            #pragma unroll
            for (int t = 0; t < 4; t++) {
                u32t b0, b1, b2r, b3;
                LDSM_X4(b0, b1, b2r, b3,
                        smb + R_WCH * 4 + 12288 + (e * 64 + t * 16 + b_r) * 48 + b_k16);
                MMA_BF16(acc[2 * t],     ah0, ah1, ah2, ah3, b0, b1);
                MMA_BF16(acc[2 * t + 1], ah0, ah1, ah2, ah3, b2r, b3);
            }
            __syncthreads();
        }
        // epilogue: pre2T[u][n'] bf16 hi/lo (+b2), then V2/c2 extension rows (cols 256..303)
        const int q = lane & 3, rw = lane >> 2;
        char* pH = smc + R_PTH * 4;
        char* pL = smc + R_PTL * 4;
        const int np0 = e * 64 + n0 + rw;
        #pragma unroll
        for (int j = 0; j < 8; j++) {
            int u = 8 * j + 2 * q;
            float2 bb = *(const float2*)(b2 + e * 64 + u);
            float v00 = acc[j][0] + bb.x, v01 = acc[j][1] + bb.y;
            float v10 = acc[j][2] + bb.x, v11 = acc[j][3] + bb.y;
            *(unsigned short*)(pH + u * ABP + np0 * 2)             = bfh(v00);
            *(unsigned short*)(pL + u * ABP + np0 * 2)             = bfh(bflo(v00));
            *(unsigned short*)(pH + (u + 1) * ABP + np0 * 2)       = bfh(v01);
            *(unsigned short*)(pL + (u + 1) * ABP + np0 * 2)       = bfh(bflo(v01));
            *(unsigned short*)(pH + u * ABP + (np0 + 8) * 2)       = bfh(v10);
            *(unsigned short*)(pL + u * ABP + (np0 + 8) * 2)       = bfh(bflo(v10));
            *(unsigned short*)(pH + (u + 1) * ABP + (np0 + 8) * 2) = bfh(v11);
            *(unsigned short*)(pL + (u + 1) * ABP + (np0 + 8) * 2) = bfh(bflo(v11));
        }
        for (int idx = tid; idx < 64 * 48; idx += NT) {
            int u = idx / 48, c = 256 + idx % 48;
            float v = (c < 288) ? V2[(c - 256) * 64 + u] : (c == 288 ? c2[u] : 0.0f);
            *(unsigned short*)(pH + u * ABP + c * 2) = bfh(v);
            *(unsigned short*)(pL + u * ABP + c * 2) = bfh(bflo(v));
        }
    }
    __syncthreads();

    // ---------------- Phase E: h2 via ONE mma.sync GEMM, K=304 (V2+c2 folded in) ----------
    {
        const int mb = wid & 3, m0 = mb * 16;
        const int ub = wid >> 2, u0 = ub * 16;
        float acc[2][4];
        acc[0][0] = acc[0][1] = acc[0][2] = acc[0][3] = 0.f;
        acc[1][0] = acc[1][1] = acc[1][2] = acc[1][3] = 0.f;
        const int al_r = (lane & 7) + ((lane >> 3) & 1) * 8;
        const int al_c8 = (lane >> 4) * 8;
        const u32t aHi = smb + R_AB_H * 4 + (m0 + al_r) * ABP;
        const u32t aLo = smb + R_AB_L * 4 + (m0 + al_r) * ABP;
        const int b_r = (lane & 7) + ((lane >> 4) << 3);
        const int b_k16 = ((lane >> 3) & 1) * 16;
        const u32t bHi = smb + R_PTH * 4 + (u0 + b_r) * ABP + b_k16;
        const u32t bLo = smb + R_PTL * 4 + (u0 + b_r) * ABP + b_k16;
        #pragma unroll 2
        for (int ck = 0; ck < 19; ck++) {
            const int k0 = ck * 16;
            u32t ah0, ah1, ah2, ah3, al0, al1, al2, al3;
            LDSM_X4(ah0, ah1, ah2, ah3, aHi + (k0 + al_c8) * 2);
            LDSM_X4(al0, al1, al2, al3, aLo + (k0 + al_c8) * 2);
            u32t bh0, bh1, bh2, bh3, bl0, bl1, bl2, bl3;
            LDSM_X4(bh0, bh1, bh2, bh3, bHi + k0 * 2);
            LDSM_X4(bl0, bl1, bl2, bl3, bLo + k0 * 2);
            MMA_BF16(acc[0], ah0, ah1, ah2, ah3, bh0, bh1);
            MMA_BF16(acc[1], ah0, ah1, ah2, ah3, bh2, bh3);
            MMA_BF16(acc[0], ah0, ah1, ah2, ah3, bl0, bl1);
            MMA_BF16(acc[1], ah0, ah1, ah2, ah3, bl2, bl3);
            MMA_BF16(acc[0], al0, al1, al2, al3, bh0, bh1);
            MMA_BF16(acc[1], al0, al1, al2, al3, bh2, bh3);
        }
        // epilogue: tanh -> F act tiles [m][u]
        const int q = lane & 3, rw = lane >> 2;
        #pragma unroll
        for (int mh = 0; mh < 2; mh++) {
            int m = m0 + rw + mh * 8;
            #pragma unroll
            for (int t = 0; t < 2; t++) {
                int u = u0 + t * 8 + 2 * q;
                float t0 = tanh_fast(acc[t][2 * mh]);
                float t1 = tanh_fast(acc[t][2 * mh + 1]);
                *(u32t*)(smc + R_FAH * 4 + m * 224 + u * 2) = bfpair(t0, t1);
                *(u32t*)(smc + R_FAL * 4 + m * 224 + u * 2) = bfpair(bflo(t0), bflo(t1));
            }
        }
        // F act tile cols 64..95 = node
        for (int idx = tid; idx < NN * 32; idx += NT) {
            int r = idx >> 5, k = 64 + (idx & 31);
            float v = smem[R_NODE + r * NODE_PITCH + (k - 64)];
            *(unsigned short*)(smc + R_FAH * 4 + r * 224 + k * 2) = bfh(v);
            *(unsigned short*)(smc + R_FAL * 4 + r * 224 + k * 2) = bfh(bflo(v));
        }
    }
    __syncthreads();

    // ---------------- Phase F: gate pre-acts via mma.sync (6 chunks, prefetched) ----------
    {
        const int uq = wid >> 2, nb = wid & 3, n0 = nb * 16;
        float acc[8][4];
        #pragma unroll
        for (int j = 0; j < 8; j++) { acc[j][0] = acc[j][1] = acc[j][2] = acc[j][3] = 0.f; }
        const int al_r = (lane & 7) + ((lane >> 3) & 1) * 8;
        const int al_c8 = (lane >> 4) * 8;
        const u32t aHi = smb + R_FAH * 4 + (n0 + al_r) * 224;
        const u32t aLo = smb + R_FAL * 4 + (n0 + al_r) * 224;
        const int b_r = (lane & 7) + ((lane >> 4) << 3);
        const int b_k16 = ((lane >> 3) & 1) * 16;
        const int i0 = tid, i1 = tid + 512;
        const int sp0 = i0 >> 9, j0 = i0 & 511, row0 = j0 >> 1, c80 = (j0 & 1) * 8;
        const int sp1 = i1 >> 9, j1 = i1 & 511, row1 = j1 >> 1, c81 = (j1 & 1) * 8;
        const char* src0 = (const char*)g_WGpack + (size_t)(sp0 * 256 + row0) * 192 + c80 * 2;
        const char* src1 = (const char*)g_WGpack + (size_t)(sp1 * 256 + row1) * 192 + c81 * 2;
        char* dst0 = smc + R_WCH * 4 + sp0 * 12288 + row0 * 48 + c80 * 2;
        char* dst1 = smc + R_WCH * 4 + sp1 * 12288 + row1 * 48 + c81 * 2;
        uint4 pf0 = *(const uint4*)(src0);
        uint4 pf1 = *(const uint4*)(src1);
        #pragma unroll 1
        for (int ck = 0; ck < 6; ck++) {
            *(uint4*)dst0 = pf0;
            *(uint4*)dst1 = pf1;
            __syncthreads();
            if (ck < 5) {
                pf0 = *(const uint4*)(src0 + (ck + 1) * 32);
                pf1 = *(const uint4*)(src1 + (ck + 1) * 32);
            }
            const int k0 = ck * 16;
            u32t ah0, ah1, ah2, ah3, al0, al1, al2, al3;
            LDSM_X4(ah0, ah1, ah2, ah3, aHi + (k0 + al_c8) * 2);
            LDSM_X4(al0, al1, al2, al3, aLo + (k0 + al_c8) * 2);
            #pragma unroll
            for (int t = 0; t < 4; t++) {
                u32t b0, b1, b2r, b3;
                LDSM_X4(b0, b1, b2r, b3,
                        smb + R_WCH * 4 + (uq * 64 + t * 16 + b_r) * 48 + b_k16);
                MMA_BF16(acc[2 * t],     ah0, ah1, ah2, ah3, b0, b1);
                MMA_BF16(acc[2 * t + 1], ah0, ah1, ah2, ah3, b2r, b3);
                MMA_BF16(acc[2 * t],     al0, al1, al2, al3, b0, b1);
                MMA_BF16(acc[2 * t + 1], al0, al1, al2, al3, b2r, b3);
            }
            #pragma unroll
            for (int t = 0; t < 4; t++) {
                u32t b0, b1, b2r, b3;
                LDSM_X4(b0, b1, b2r, b3,
                        smb + R_WCH * 4 + 12288 + (uq * 64 + t * 16 + b_r) * 48 + b_k16);
                MMA_BF16(acc[2 * t],     ah0, ah1, ah2, ah3, b0, b1);
                MMA_BF16(acc[2 * t + 1], ah0, ah1, ah2, ah3, b2r, b3);
            }
            __syncthreads();
        }
        // epilogue: pi/pj (+bias) over dead AB region
        const int q = lane & 3, rw = lane >> 2;
        #pragma unroll
        for (int j = 0; j < 8; j++) {
            int up = uq * 64 + 8 * j + 2 * q;
            int mat = up >> 7, uu = up & 127;
            float2 bb = *(const float2*)((mat ? bj : bi) + uu);
            int base = (mat ? R_PJ : R_PI) + (n0 + rw) * PI_PITCH + uu;
            smem[base]                    = acc[j][0] + bb.x;
            smem[base + 1]                = acc[j][1] + bb.y;
            smem[base + 8 * PI_PITCH]     = acc[j][2] + bb.x;
            smem[base + 8 * PI_PITCH + 1] = acc[j][3] + bb.y;
        }
    }
    __syncthreads();

    // ---------------- Phase G: out[b][u] = tanh(sum_n sigmoid(pi)*tanh(pj)) ----------------
    {
        const int qg = tid >> 7, u = tid & 127;
        float s = 0.0f;
        #pragma unroll
        for (int i = 0; i < 16; i++) {
            int n = qg * 16 + i;
            float pi = smem[R_PI + n * PI_PITCH + u];
            float pj = smem[R_PJ + n * PI_PITCH + u];
            s += sigmoid_fast(pi) * tanh_fast(pj);
        }
        smem[R_RED + qg * UAC + u] = s;
    }
    __syncthreads();
    if (tid < UAC) {
        float s = smem[R_RED + tid] + smem[R_RED + UAC + tid]
                + smem[R_RED + 2 * UAC + tid] + smem[R_RED + 3 * UAC + tid];
        out[(size_t)b * UAC + tid] = tanh_fast(s);
    }
}

extern "C" void kernel_launch(void* const* d_in, const int* in_sizes, int n_in,
                              void* d_out, int out_size) {
    (void)in_sizes; (void)n_in; (void)out_size;
    const float* adjacency = (const float*)d_in[0];
    const float* node = (const float*)d_in[2];
    const float* W1 = (const float*)d_in[3];
    const float* b1 = (const float*)d_in[4];
    const float* V1 = (const float*)d_in[5];
    const float* c1 = (const float*)d_in[6];
    const float* W2 = (const float*)d_in[7];
    const float* b2 = (const float*)d_in[8];
    const float* V2 = (const float*)d_in[9];
    const float* c2 = (const float*)d_in[10];
    const float* Wi = (const float*)d_in[11];
    const float* bi = (const float*)d_in[12];
    const float* Wj = (const float*)d_in[13];
    const float* bj = (const float*)d_in[14];

    preconv_kernel<<<344, 256>>>(W2, Wi, Wj, W1, V1, b1, c1);
    cudaFuncSetAttribute(encoder_kernel,
                         cudaFuncAttributeMaxDynamicSharedMemorySize, SMEM_BYTES);
    encoder_kernel<<<BATCH, NT, SMEM_BYTES>>>(adjacency, node,
                                              b2, V2, c2,
                                              bi, bj,
                                              (float*)d_out);
}